// round 3
// baseline (speedup 1.0000x reference)
#include <cuda_runtime.h>

#define B_    64
#define T_    1024
#define D_    128
#define NE    512
#define NCODE 513
#define ROWS  (B_ * T_)   // 65536

// ---- output layout (float32, tuple order) ----
#define OFF_KH  0
#define OFF_ENC 8388608
#define OFF_V   8454144
#define OFF_LH  8454145
#define OFF_LNX 8519681
#define OFF_EM  8585217
#define OFF_LED 8585218

// ---- scratch (static device globals; no allocations) ----
__device__ float         g_dot[(size_t)ROWS * NE];   // dot(ks,e_n) for n<512 (128MB)
__device__ float         g_ks2[ROWS];
__device__ float         g_e2[NCODE];
__device__ int           g_minidx[ROWS];
__device__ unsigned      g_move[(size_t)ROWS * 16];  // 512 move bits per row
__device__ unsigned short g_tbl[(size_t)B_ * 15 * 512]; // chunk transition tables
__device__ int           g_ent[B_ * 16];             // chunk entry states
__device__ int           g_enc[ROWS];
__device__ float         g_energy[ROWS];
__device__ float         g_pE[B_], g_pL[B_];
__device__ int           g_rng[B_];

// ============================================================
// K0: row sums of squares for key_soft (65536 rows) and emb (513 rows)
// ============================================================
__global__ __launch_bounds__(256) void k_sq(const float* __restrict__ ks,
                                            const float* __restrict__ emb) {
    int gw   = (blockIdx.x * 256 + threadIdx.x) >> 5;
    int lane = threadIdx.x & 31;
    if (gw < ROWS) {
        const float4* p = (const float4*)ks + (size_t)gw * 32;
        float4 v = p[lane];
        float s = v.x * v.x;
        s = fmaf(v.y, v.y, s);
        s = fmaf(v.z, v.z, s);
        s = fmaf(v.w, v.w, s);
#pragma unroll
        for (int off = 16; off; off >>= 1) s += __shfl_xor_sync(0xffffffffu, s, off);
        if (lane == 0) g_ks2[gw] = s;
    } else {
        int r = gw - ROWS;
        if (r < NCODE) {
            const float4* p = (const float4*)emb + (size_t)r * 32;
            float4 v = p[lane];
            float s = v.x * v.x;
            s = fmaf(v.y, v.y, s);
            s = fmaf(v.z, v.z, s);
            s = fmaf(v.w, v.w, s);
#pragma unroll
            for (int off = 16; off; off >>= 1) s += __shfl_xor_sync(0xffffffffu, s, off);
            if (lane == 0) g_e2[r] = s;
        }
    }
}

// ============================================================
// K1: fp32 GEMM  dot[m][n] = sum_k ks[m][k]*emb[n][k], n < 512
// BM=128, BN=64, BK=32, 256 threads, 8x4 per-thread tile
// ============================================================
__global__ __launch_bounds__(256) void k_gemm(const float* __restrict__ A,
                                              const float* __restrict__ Bw,
                                              float* __restrict__ C) {
    __shared__ float As[32][132];
    __shared__ float Bs[32][68];
    const int m0  = blockIdx.y * 128;
    const int n0  = blockIdx.x * 64;
    const int tid = threadIdx.x;
    const int tx  = tid & 15;
    const int ty  = tid >> 4;
    float acc[8][4];
#pragma unroll
    for (int i = 0; i < 8; i++)
#pragma unroll
        for (int j = 0; j < 4; j++) acc[i][j] = 0.0f;

    for (int k0 = 0; k0 < 128; k0 += 32) {
#pragma unroll
        for (int r = 0; r < 16; r++) {
            int idx = tid + r * 256;                      // 0..4095
            As[idx & 31][idx >> 5] =
                A[(size_t)(m0 + (idx >> 5)) * 128 + k0 + (idx & 31)];
        }
#pragma unroll
        for (int r = 0; r < 8; r++) {
            int idx = tid + r * 256;                      // 0..2047
            Bs[idx & 31][idx >> 5] =
                Bw[(size_t)(n0 + (idx >> 5)) * 128 + k0 + (idx & 31)];
        }
        __syncthreads();
#pragma unroll
        for (int kk = 0; kk < 32; kk++) {
            float a[8], b[4];
#pragma unroll
            for (int i = 0; i < 8; i++) a[i] = As[kk][ty * 8 + i];
#pragma unroll
            for (int j = 0; j < 4; j++) b[j] = Bs[kk][tx * 4 + j];
#pragma unroll
            for (int i = 0; i < 8; i++)
#pragma unroll
                for (int j = 0; j < 4; j++) acc[i][j] = fmaf(a[i], b[j], acc[i][j]);
        }
        __syncthreads();
    }
#pragma unroll
    for (int i = 0; i < 8; i++) {
        float4 v = make_float4(acc[i][0], acc[i][1], acc[i][2], acc[i][3]);
        *(float4*)&C[(size_t)(m0 + ty * 8 + i) * 512 + n0 + tx * 4] = v;
    }
}

// ============================================================
// K2: per-row d assembly, argmin (first occurrence), move bits.
// n=512 column's dot computed here directly.
// ============================================================
__global__ __launch_bounds__(512) void k_rowstats(const float* __restrict__ ks,
                                                  const float* __restrict__ emb) {
    const int row = blockIdx.x;
    const int tid = threadIdx.x;
    __shared__ float sd[NCODE];
    __shared__ float wv[16];
    __shared__ int   wi[16];

    float ks2 = g_ks2[row];
    sd[tid] = (ks2 + g_e2[tid]) - 2.0f * g_dot[(size_t)row * 512 + tid];
    if (tid < 32) {
        const float4* k4 = (const float4*)ks + (size_t)row * 32;
        const float4* e4 = (const float4*)emb + (size_t)512 * 32;
        float4 a = k4[tid], e = e4[tid];
        float s = a.x * e.x;
        s = fmaf(a.y, e.y, s);
        s = fmaf(a.z, e.z, s);
        s = fmaf(a.w, e.w, s);
#pragma unroll
        for (int off = 16; off; off >>= 1) s += __shfl_xor_sync(0xffffffffu, s, off);
        if (tid == 0) sd[512] = (ks2 + g_e2[512]) - 2.0f * s;
    }
    __syncthreads();

    // move bits: advance iff d[j] > d[min(j+1,511)]
    int jn = (tid < 511) ? tid + 1 : 511;
    unsigned bal = __ballot_sync(0xffffffffu, sd[tid] > sd[jn]);
    if ((tid & 31) == 0) g_move[(size_t)row * 16 + (tid >> 5)] = bal;

    // argmin over 513 with first-occurrence tie-break (lexicographic (val, idx) min)
    float v = sd[tid];
    int   ix = tid;
    if (tid == 0) {
        float v2 = sd[512];
        if (v2 < v) { v = v2; ix = 512; }
    }
#pragma unroll
    for (int off = 16; off; off >>= 1) {
        float ov = __shfl_xor_sync(0xffffffffu, v, off);
        int   oi = __shfl_xor_sync(0xffffffffu, ix, off);
        if (ov < v || (ov == v && oi < ix)) { v = ov; ix = oi; }
    }
    if ((tid & 31) == 0) { wv[tid >> 5] = v; wi[tid >> 5] = ix; }
    __syncthreads();
    if (tid < 32) {
        float v2 = (tid < 16) ? wv[tid] : 3.0e38f;
        int   i2 = (tid < 16) ? wi[tid] : 0x7fffffff;
#pragma unroll
        for (int off = 16; off; off >>= 1) {
            float ov = __shfl_xor_sync(0xffffffffu, v2, off);
            int   oi = __shfl_xor_sync(0xffffffffu, i2, off);
            if (ov < v2 || (ov == v2 && oi < i2)) { v2 = ov; i2 = oi; }
        }
        if (tid == 0) g_minidx[row] = i2;
    }
}

// ============================================================
// K3a: chunk transition tables. chunk c (0..14) covers transitions
// t = c*64+1 .. c*64+64. 512 threads = all start states.
// ============================================================
__global__ __launch_bounds__(512) void k_scantbl(void) {
    const int c   = blockIdx.x;     // 0..14
    const int b   = blockIdx.y;
    const int tid = threadIdx.x;
    __shared__ unsigned mw[64][16];
    const int t0 = c * 64 + 1;
#pragma unroll
    for (int r = 0; r < 2; r++) {
        int i = tid + r * 512;
        mw[i >> 4][i & 15] =
            g_move[(size_t)(b * 1024 + t0 + (i >> 4)) * 16 + (i & 15)];
    }
    __syncthreads();
    int ind = tid;
    for (int s = 0; s < 64; s++) ind += (mw[s][ind >> 5] >> (ind & 31)) & 1;
    g_tbl[((size_t)b * 15 + c) * 512 + tid] = (unsigned short)ind;
}

// ============================================================
// K3b: compose chunk tables -> chunk entry states per batch
// ============================================================
__global__ void k_entries(const unsigned char* __restrict__ mask) {
    int b = threadIdx.x;
    if (b >= B_) return;
    int ind = g_minidx[b * 1024];
    if (ind > 511) ind = 511;
    if (mask[b]) ind = 0;
    g_ent[b * 16] = ind;
    for (int c = 0; c < 15; c++) {
        ind = g_tbl[((size_t)b * 15 + c) * 512 + ind];
        g_ent[b * 16 + c + 1] = ind;
    }
}

// ============================================================
// K3c: re-simulate within each chunk from the known entry state
// and emit enc[b][t]. thread s emits t = c*64+s.
// ============================================================
__global__ __launch_bounds__(64) void k_emit_enc(void) {
    const int c   = blockIdx.x;     // 0..15
    const int b   = blockIdx.y;
    const int tid = threadIdx.x;
    __shared__ unsigned mw[63][16];
    const int t0 = c * 64 + 1;
    for (int i = tid; i < 63 * 16; i += 64)
        mw[i >> 4][i & 15] =
            g_move[(size_t)(b * 1024 + t0 + (i >> 4)) * 16 + (i & 15)];
    __syncthreads();
    int ind = g_ent[b * 16 + c];
    for (int s = 0; s < tid; s++) ind += (mw[s][ind >> 5] >> (ind & 31)) & 1;
    g_enc[b * 1024 + c * 64 + tid] = ind;
}

// ============================================================
// K4: fused gathers + losses + key_hard + energy. One warp per (b,t).
// ============================================================
__global__ __launch_bounds__(256) void k_final(const float* __restrict__ ks,
                                               const float* __restrict__ emb,
                                               float* __restrict__ out) {
    const int row  = blockIdx.x * 8 + (threadIdx.x >> 5);
    const int lane = threadIdx.x & 31;
    const float4* k4 = (const float4*)ks + (size_t)row * 32;
    const float4* e4 = (const float4*)emb;

    int here = g_enc[row];
    int nxt  = here + 1; if (nxt > 511) nxt = 511;
    int mi   = g_minidx[row];

    float4 a  = k4[lane];
    float4 eh = e4[(size_t)here * 32 + lane];
    float4 en = e4[(size_t)nxt * 32 + lane];
    float4 em = e4[(size_t)mi * 32 + lane];

    float sh, sn, sm;
    {
        float d0 = a.x - eh.x, d1 = a.y - eh.y, d2 = a.z - eh.z, d3 = a.w - eh.w;
        sh = d0 * d0; sh = fmaf(d1, d1, sh); sh = fmaf(d2, d2, sh); sh = fmaf(d3, d3, sh);
    }
    {
        float d0 = a.x - en.x, d1 = a.y - en.y, d2 = a.z - en.z, d3 = a.w - en.w;
        sn = d0 * d0; sn = fmaf(d1, d1, sn); sn = fmaf(d2, d2, sn); sn = fmaf(d3, d3, sn);
    }
    {
        float d0 = a.x - em.x, d1 = a.y - em.y, d2 = a.z - em.z, d3 = a.w - em.w;
        sm = d0 * d0; sm = fmaf(d1, d1, sm); sm = fmaf(d2, d2, sm); sm = fmaf(d3, d3, sm);
    }
#pragma unroll
    for (int off = 16; off; off >>= 1) {
        sh += __shfl_xor_sync(0xffffffffu, sh, off);
        sn += __shfl_xor_sync(0xffffffffu, sn, off);
        sm += __shfl_xor_sync(0xffffffffu, sm, off);
    }

    // key_hard = ks + (kh_here - ks), mirrored elementwise in fp32
    float4 o;
    o.x = a.x + (eh.x - a.x);
    o.y = a.y + (eh.y - a.y);
    o.z = a.z + (eh.z - a.z);
    o.w = a.w + (eh.w - a.w);
    ((float4*)(out + OFF_KH))[(size_t)row * 32 + lane] = o;

    if (lane == 0) {
        float Lh = sh + sh * 0.2f;
        float Ln = sn + sn * 0.2f;
        float Lm = sm + sm * 0.2f;
        float dif = sn - sh;
        float energy = dif + dif * 0.2f;
        float lmh = (Lm < Lh) ? Lm : 0.0f;
        float lmn = (Lm < Ln) ? Lm : 0.0f;
        out[OFF_LH  + row] = (Lh - Ln) - lmh;
        out[OFF_LNX + row] = (Ln - Lh) - lmn;
        out[OFF_ENC + row] = (float)here;
        g_energy[row] = energy;
    }
}

// ============================================================
// K5: per-batch reductions (deterministic order)
// ============================================================
__global__ __launch_bounds__(256) void k_reduce_b(void) {
    const int b   = blockIdx.x;
    const int tid = threadIdx.x;
    __shared__ float sE[256], sL[256];
    __shared__ int   sMn[256], sMx[256];
    const float* eb = g_energy + b * 1024;
    const int*   cb = g_enc + b * 1024;

    float aE = 0.0f, aL = 0.0f;
    int mn = 1 << 30, mx = -1;
    for (int t = tid; t < 1024; t += 256) {
        aE += eb[t];
        int cv = cb[t];
        mn = min(mn, cv);
        mx = max(mx, cv);
    }
    const float EPS = (float)(1e-6 / 512.0);
    for (int t = tid + 1; t < 1024; t += 256) {
        float ch = (cb[t] != cb[t - 1]) ? 0.0f : (eb[t] - eb[t - 1]);
        aL += fmaxf(ch + EPS, 0.0f);
    }
    sE[tid] = aE; sL[tid] = aL; sMn[tid] = mn; sMx[tid] = mx;
    __syncthreads();
    for (int s = 128; s; s >>= 1) {
        if (tid < s) {
            sE[tid] += sE[tid + s];
            sL[tid] += sL[tid + s];
            sMn[tid] = min(sMn[tid], sMn[tid + s]);
            sMx[tid] = max(sMx[tid], sMx[tid + s]);
        }
        __syncthreads();
    }
    if (tid == 0) {
        g_pE[b]  = sE[0];
        g_pL[b]  = sL[0];
        g_rng[b] = sMx[0] - sMn[0];
    }
}

// ============================================================
// K6: final scalars
// ============================================================
__global__ void k_scalars(float* __restrict__ out) {
    int tid = threadIdx.x;  // 64
    __shared__ float sE[64], sL[64];
    __shared__ int   sR[64];
    sE[tid] = g_pE[tid]; sL[tid] = g_pL[tid]; sR[tid] = g_rng[tid];
    __syncthreads();
    for (int s = 32; s; s >>= 1) {
        if (tid < s) {
            sE[tid] += sE[tid + s];
            sL[tid] += sL[tid + s];
            sR[tid] = max(sR[tid], sR[tid + s]);
        }
        __syncthreads();
    }
    if (tid == 0) {
        out[OFF_EM]  = sE[0] / 65536.0f;
        out[OFF_LED] = sL[0] / 65472.0f;
        out[OFF_V]   = (float)sR[0];
    }
}

// ============================================================
extern "C" void kernel_launch(void* const* d_in, const int* in_sizes, int n_in,
                              void* d_out, int out_size) {
    const float* ks = nullptr;
    const float* emb = nullptr;
    const unsigned char* mask = nullptr;
    for (int i = 0; i < n_in; i++) {
        if (in_sizes[i] == ROWS * D_)        ks   = (const float*)d_in[i];
        else if (in_sizes[i] == NCODE * D_)  emb  = (const float*)d_in[i];
        else if (in_sizes[i] == B_)          mask = (const unsigned char*)d_in[i];
    }
    float* out = (float*)d_out;

    // pointer into the same scratch symbol for the GEMM output
    // (kernels reference g_dot directly; pass it via a device-symbol kernel arg-free path)
    // K1 writes via parameter: use the global directly inside a wrapper lambda-style launch.

    // K0: sums of squares (65536 + 513 rows; warp per row)
    {
        int warps = ROWS + NCODE;
        int blocks = (warps * 32 + 255) / 256;
        k_sq<<<blocks, 256>>>(ks, emb);
    }
    // K1: GEMM into g_dot — obtain device pointer via kernel referencing global:
    // (pass nullptr trick avoided: just let k_gemm take C and give it the symbol
    //  through a device-side constant is unnecessary — use cudaGetSymbolAddress once
    //  per call; it is a pure query, not an allocation, and is capture-safe.)
    {
        void* dotp = nullptr;
        cudaGetSymbolAddress(&dotp, g_dot);
        k_gemm<<<dim3(8, 512), 256>>>(ks, emb, (float*)dotp);
    }
    // K2: per-row d, argmin, move bits
    k_rowstats<<<ROWS, 512>>>(ks, emb);
    // K3: chunked monotone scan
    k_scantbl<<<dim3(15, B_), 512>>>();
    k_entries<<<1, 64>>>(mask);
    k_emit_enc<<<dim3(16, B_), 64>>>();
    // K4: fused epilogue
    k_final<<<ROWS / 8, 256>>>(ks, emb, out);
    // K5/K6: reductions
    k_reduce_b<<<B_, 256>>>();
    k_scalars<<<1, 64>>>(out);
}

// round 6
// speedup vs baseline: 1.1233x; 1.1233x over previous
#include <cuda_runtime.h>
#include <cstdint>

typedef unsigned long long ull;

#define B_    64
#define T_    1024
#define D_    128
#define NE    512
#define NCODE 513
#define ROWS  (B_ * T_)   // 65536

// ---- output layout (float32, tuple order) ----
#define OFF_KH  0
#define OFF_ENC 8388608
#define OFF_V   8454144
#define OFF_LH  8454145
#define OFF_LNX 8519681
#define OFF_EM  8585217
#define OFF_LED 8585218

// ---- scratch ----
__device__ float          g_e2[NCODE];
__device__ float          g_ks2[ROWS];
__device__ int            g_minidx[ROWS];
__device__ unsigned       g_move[(size_t)ROWS * 16];
__device__ unsigned short g_tbl[(size_t)B_ * 15 * 512];
__device__ int            g_ent[B_ * 16];
__device__ int            g_enc[ROWS];
__device__ float          g_energy[ROWS];
__device__ float          g_pE[B_], g_pL[B_];
__device__ int            g_rng[B_];

// ============================================================
// K0: row sums of squares for key_soft and emb (warp per row)
// ============================================================
__global__ __launch_bounds__(256) void k_sq(const float* __restrict__ ks,
                                            const float* __restrict__ emb) {
    int gw   = (blockIdx.x * 256 + threadIdx.x) >> 5;
    int lane = threadIdx.x & 31;
    if (gw < ROWS) {
        const float4* p = (const float4*)ks + (size_t)gw * 32;
        float4 v = p[lane];
        float s = v.x * v.x;
        s = fmaf(v.y, v.y, s);
        s = fmaf(v.z, v.z, s);
        s = fmaf(v.w, v.w, s);
#pragma unroll
        for (int off = 16; off; off >>= 1) s += __shfl_xor_sync(0xffffffffu, s, off);
        if (lane == 0) g_ks2[gw] = s;
    } else {
        int r = gw - ROWS;
        if (r < NCODE) {
            const float4* p = (const float4*)emb + (size_t)r * 32;
            float4 v = p[lane];
            float s = v.x * v.x;
            s = fmaf(v.y, v.y, s);
            s = fmaf(v.z, v.z, s);
            s = fmaf(v.w, v.w, s);
#pragma unroll
            for (int off = 16; off; off >>= 1) s += __shfl_xor_sync(0xffffffffu, s, off);
            if (lane == 0) g_e2[r] = s;
        }
    }
}

// ============================================================
// K1: fused FFMA2 GEMM (BM=64, BN=512, K=128) + epilogue
//     (d assembly, argmin over 513, move bits). No g_dot.
// ============================================================
#define E2S_OFF   0
#define ASD_OFF   2176                     // 16 kk x 64 dup-pairs x 8B = 8KB
#define BS_OFF    10368                    // 16 kk x 2048B            = 32KB
#define SD_OFF    2176                     // 64 x 536 floats (reuses tiles)
#define SD_STRIDE 536
#define SMEM_BYTES 139392

__device__ __forceinline__ void fma2(ull& d, ull a, ull b) {
    asm("fma.rn.f32x2 %0, %1, %2, %0;" : "+l"(d) : "l"(a), "l"(b));
}

__global__ void __launch_bounds__(512, 1)
k_gemm_fused(const float* __restrict__ A, const float* __restrict__ E) {
    extern __shared__ char smem[];
    float* e2s = (float*)(smem + E2S_OFF);
    const int tid = threadIdx.x;
    const int mb  = blockIdx.x;
    const int tx  = tid & 63;
    const int ty  = tid >> 6;

    // FIX (R5): cover ALL 513 entries — e2s[512] was never initialized with
    // 512 threads, making minidx depend on stale smem residue across replays.
    for (int i = tid; i < NCODE; i += 512) e2s[i] = g_e2[i];

    ull acc[32];
#pragma unroll
    for (int i = 0; i < 32; i++) acc[i] = 0ull;

    float4 ra, rb[4];
    // prefetch chunk 0
    if (tid < 256) {
        int r = tid >> 2, kq = (tid & 3) * 4;
        ra = *(const float4*)(A + (size_t)(mb * 64 + r) * 128 + kq);
    }
#pragma unroll
    for (int j = 0; j < 4; j++) {
        int m = tid + j * 512;
        int n = m >> 2, kq = (m & 3) * 4;
        rb[j] = *(const float4*)(E + (size_t)n * 128 + kq);
    }

    for (int c = 0; c < 8; c++) {
        // ---- store staged chunk to smem ----
        if (tid < 256) {
            int r = tid >> 2, kq = (tid & 3) * 4;
            const float* v = &ra.x;
#pragma unroll
            for (int q = 0; q < 4; q++) {
                unsigned u = __float_as_uint(v[q]);
                ull p = ((ull)u << 32) | (ull)u;
                *(ull*)(smem + ASD_OFF + (size_t)(kq + q) * 512 + r * 8) = p;
            }
        }
#pragma unroll
        for (int j = 0; j < 4; j++) {
            int m = tid + j * 512;
            int n = m >> 2, kq = (m & 3) * 4;
            int p = n >> 1, h = n & 1;
            const float* v = &rb[j].x;
#pragma unroll
            for (int q = 0; q < 4; q++) {
                *(float*)(smem + BS_OFF + (size_t)(kq + q) * 2048 +
                          (p & 3) * 512 + (p >> 2) * 8 + h * 4) = v[q];
            }
        }
        __syncthreads();
        // ---- prefetch next chunk (overlaps with compute) ----
        if (c < 7) {
            int k0 = (c + 1) * 16;
            if (tid < 256) {
                int r = tid >> 2, kq = (tid & 3) * 4;
                ra = *(const float4*)(A + (size_t)(mb * 64 + r) * 128 + k0 + kq);
            }
#pragma unroll
            for (int j = 0; j < 4; j++) {
                int m = tid + j * 512;
                int n = m >> 2, kq = (m & 3) * 4;
                rb[j] = *(const float4*)(E + (size_t)n * 128 + k0 + kq);
            }
        }
        // ---- compute 16 k-steps ----
#pragma unroll
        for (int kk = 0; kk < 16; kk++) {
            ull aa[8];
            const ulonglong2* ap =
                (const ulonglong2*)(smem + ASD_OFF + (size_t)kk * 512 + ty * 64);
#pragma unroll
            for (int i = 0; i < 4; i++) {
                ulonglong2 w = ap[i];
                aa[2 * i] = w.x; aa[2 * i + 1] = w.y;
            }
            ull bb[4];
#pragma unroll
            for (int q = 0; q < 4; q++)
                bb[q] = *(const ull*)(smem + BS_OFF + (size_t)kk * 2048 +
                                      q * 512 + tx * 8);
#pragma unroll
            for (int i = 0; i < 8; i++)
#pragma unroll
                for (int q = 0; q < 4; q++)
                    fma2(acc[i * 4 + q], aa[i], bb[q]);
        }
        __syncthreads();
    }

    // ---- dump dots to smem d-buffer ----
    float* sd = (float*)(smem + SD_OFF);
#pragma unroll
    for (int i = 0; i < 8; i++) {
        int row = ty * 8 + i;
#pragma unroll
        for (int q = 0; q < 4; q++) {
            int col = 8 * tx + 2 * q;
            *(ull*)(sd + (size_t)row * SD_STRIDE + col) = acc[i * 4 + q];
        }
    }
    __syncthreads();

    // ---- row scan: 8 threads per row, strided cols (conflict-free) ----
    const int t   = tid & 7;
    const int rid = tid >> 3;
    const int row_g = mb * 64 + rid;
    const float ks2 = g_ks2[row_g];

    // dot with code 512
    float dt = 0.0f;
    {
        const float4* kr = (const float4*)A + (size_t)row_g * 32;
        const float4* er = (const float4*)E + (size_t)512 * 32;
#pragma unroll
        for (int j = 0; j < 4; j++) {
            float4 a = kr[t * 4 + j];
            float4 e = __ldg(&er[t * 4 + j]);
            dt = fmaf(a.x, e.x, dt); dt = fmaf(a.y, e.y, dt);
            dt = fmaf(a.z, e.z, dt); dt = fmaf(a.w, e.w, dt);
        }
#pragma unroll
        for (int o = 1; o < 8; o <<= 1) dt += __shfl_xor_sync(0xffffffffu, dt, o);
    }
    float d512 = (ks2 + e2s[512]) - 2.0f * dt;

    const float* sdr = sd + (size_t)rid * SD_STRIDE;
    float best = 3.4e38f;
    int   bi = 0;
    float dprev = 0.0f;
    unsigned word = 0;
    const unsigned shift = (unsigned)(tid & 24);  // 8 * (lane group)
#pragma unroll 4
    for (int k = 0; k < 64; k++) {
        float d = (ks2 + e2s[8 * k + t]) - 2.0f * sdr[8 * k + t];
        if (k > 0) {
            float dnb = __shfl_down_sync(0xffffffffu, dprev, 1, 8);
            float d0  = __shfl_sync(0xffffffffu, d, 0, 8);
            float nxt = (t == 7) ? d0 : dnb;
            unsigned Bb = __ballot_sync(0xffffffffu, dprev > nxt);
            word |= ((Bb >> shift) & 0xFFu) << (((k - 1) & 3) * 8);
            if (((k - 1) & 3) == 3) {
                if (t == 0) g_move[(size_t)row_g * 16 + ((k - 1) >> 2)] = word;
                word = 0;
            }
        }
        if (d < best) { best = d; bi = 8 * k + t; }
        dprev = d;
    }
    {
        float dnb = __shfl_down_sync(0xffffffffu, dprev, 1, 8);
        unsigned Bb = __ballot_sync(0xffffffffu, (t < 7) && (dprev > dnb));
        word |= ((Bb >> shift) & 0xFFu) << 24;
        if (t == 0) g_move[(size_t)row_g * 16 + 15] = word;
    }
#pragma unroll
    for (int o = 1; o < 8; o <<= 1) {
        float ov = __shfl_xor_sync(0xffffffffu, best, o);
        int   oi = __shfl_xor_sync(0xffffffffu, bi, o);
        if (ov < best || (ov == best && oi < bi)) { best = ov; bi = oi; }
    }
    if (d512 < best) bi = 512;
    if (t == 0) g_minidx[row_g] = bi;
}

// ============================================================
// K3a: chunk transition tables
// ============================================================
__global__ __launch_bounds__(512) void k_scantbl(void) {
    const int c   = blockIdx.x;     // 0..14
    const int b   = blockIdx.y;
    const int tid = threadIdx.x;
    __shared__ unsigned mw[64][16];
    const int t0 = c * 64 + 1;
#pragma unroll
    for (int r = 0; r < 2; r++) {
        int i = tid + r * 512;
        mw[i >> 4][i & 15] =
            g_move[(size_t)(b * 1024 + t0 + (i >> 4)) * 16 + (i & 15)];
    }
    __syncthreads();
    int ind = tid;
    for (int s = 0; s < 64; s++) ind += (mw[s][ind >> 5] >> (ind & 31)) & 1;
    g_tbl[((size_t)b * 15 + c) * 512 + tid] = (unsigned short)ind;
}

// ============================================================
// K3b: compose chunk tables -> chunk entry states per batch
// ============================================================
__global__ void k_entries(const unsigned char* __restrict__ mask) {
    int b = threadIdx.x;
    if (b >= B_) return;
    int ind = g_minidx[b * 1024];
    if (ind > 511) ind = 511;
    if (mask[b]) ind = 0;
    g_ent[b * 16] = ind;
    for (int c = 0; c < 15; c++) {
        ind = g_tbl[((size_t)b * 15 + c) * 512 + ind];
        g_ent[b * 16 + c + 1] = ind;
    }
}

// ============================================================
// K3c: re-simulate within chunk from entry state, emit enc
// ============================================================
__global__ __launch_bounds__(64) void k_emit_enc(void) {
    const int c   = blockIdx.x;     // 0..15
    const int b   = blockIdx.y;
    const int tid = threadIdx.x;
    __shared__ unsigned mw[63][16];
    const int t0 = c * 64 + 1;
    for (int i = tid; i < 63 * 16; i += 64)
        mw[i >> 4][i & 15] =
            g_move[(size_t)(b * 1024 + t0 + (i >> 4)) * 16 + (i & 15)];
    __syncthreads();
    int ind = g_ent[b * 16 + c];
    for (int s = 0; s < tid; s++) ind += (mw[s][ind >> 5] >> (ind & 31)) & 1;
    g_enc[b * 1024 + c * 64 + tid] = ind;
}

// ============================================================
// K4: fused gathers + losses + key_hard + energy. Warp per (b,t).
// ============================================================
__global__ __launch_bounds__(256) void k_final(const float* __restrict__ ks,
                                               const float* __restrict__ emb,
                                               float* __restrict__ out) {
    const int row  = blockIdx.x * 8 + (threadIdx.x >> 5);
    const int lane = threadIdx.x & 31;
    const float4* k4 = (const float4*)ks + (size_t)row * 32;
    const float4* e4 = (const float4*)emb;

    int here = g_enc[row];
    int nxt  = here + 1; if (nxt > 511) nxt = 511;
    int mi   = g_minidx[row];

    float4 a  = k4[lane];
    float4 eh = e4[(size_t)here * 32 + lane];
    float4 en = e4[(size_t)nxt * 32 + lane];
    float4 em = e4[(size_t)mi * 32 + lane];

    float sh, sn, sm;
    {
        float d0 = a.x - eh.x, d1 = a.y - eh.y, d2 = a.z - eh.z, d3 = a.w - eh.w;
        sh = d0 * d0; sh = fmaf(d1, d1, sh); sh = fmaf(d2, d2, sh); sh = fmaf(d3, d3, sh);
    }
    {
        float d0 = a.x - en.x, d1 = a.y - en.y, d2 = a.z - en.z, d3 = a.w - en.w;
        sn = d0 * d0; sn = fmaf(d1, d1, sn); sn = fmaf(d2, d2, sn); sn = fmaf(d3, d3, sn);
    }
    {
        float d0 = a.x - em.x, d1 = a.y - em.y, d2 = a.z - em.z, d3 = a.w - em.w;
        sm = d0 * d0; sm = fmaf(d1, d1, sm); sm = fmaf(d2, d2, sm); sm = fmaf(d3, d3, sm);
    }
#pragma unroll
    for (int off = 16; off; off >>= 1) {
        sh += __shfl_xor_sync(0xffffffffu, sh, off);
        sn += __shfl_xor_sync(0xffffffffu, sn, off);
        sm += __shfl_xor_sync(0xffffffffu, sm, off);
    }

    float4 o;
    o.x = a.x + (eh.x - a.x);
    o.y = a.y + (eh.y - a.y);
    o.z = a.z + (eh.z - a.z);
    o.w = a.w + (eh.w - a.w);
    ((float4*)(out + OFF_KH))[(size_t)row * 32 + lane] = o;

    if (lane == 0) {
        float Lh = sh + sh * 0.2f;
        float Ln = sn + sn * 0.2f;
        float Lm = sm + sm * 0.2f;
        float dif = sn - sh;
        float energy = dif + dif * 0.2f;
        float lmh = (Lm < Lh) ? Lm : 0.0f;
        float lmn = (Lm < Ln) ? Lm : 0.0f;
        out[OFF_LH  + row] = (Lh - Ln) - lmh;
        out[OFF_LNX + row] = (Ln - Lh) - lmn;
        out[OFF_ENC + row] = (float)here;
        g_energy[row] = energy;
    }
}

// ============================================================
// K5: per-batch reductions
// ============================================================
__global__ __launch_bounds__(256) void k_reduce_b(void) {
    const int b   = blockIdx.x;
    const int tid = threadIdx.x;
    __shared__ float sE[256], sL[256];
    __shared__ int   sMn[256], sMx[256];
    const float* eb = g_energy + b * 1024;
    const int*   cb = g_enc + b * 1024;

    float aE = 0.0f, aL = 0.0f;
    int mn = 1 << 30, mx = -1;
    for (int t = tid; t < 1024; t += 256) {
        aE += eb[t];
        int cv = cb[t];
        mn = min(mn, cv);
        mx = max(mx, cv);
    }
    const float EPS = (float)(1e-6 / 512.0);
    for (int t = tid + 1; t < 1024; t += 256) {
        float ch = (cb[t] != cb[t - 1]) ? 0.0f : (eb[t] - eb[t - 1]);
        aL += fmaxf(ch + EPS, 0.0f);
    }
    sE[tid] = aE; sL[tid] = aL; sMn[tid] = mn; sMx[tid] = mx;
    __syncthreads();
    for (int s = 128; s; s >>= 1) {
        if (tid < s) {
            sE[tid] += sE[tid + s];
            sL[tid] += sL[tid + s];
            sMn[tid] = min(sMn[tid], sMn[tid + s]);
            sMx[tid] = max(sMx[tid], sMx[tid + s]);
        }
        __syncthreads();
    }
    if (tid == 0) {
        g_pE[b]  = sE[0];
        g_pL[b]  = sL[0];
        g_rng[b] = sMx[0] - sMn[0];
    }
}

// ============================================================
// K6: final scalars
// ============================================================
__global__ void k_scalars(float* __restrict__ out) {
    int tid = threadIdx.x;  // 64
    __shared__ float sE[64], sL[64];
    __shared__ int   sR[64];
    sE[tid] = g_pE[tid]; sL[tid] = g_pL[tid]; sR[tid] = g_rng[tid];
    __syncthreads();
    for (int s = 32; s; s >>= 1) {
        if (tid < s) {
            sE[tid] += sE[tid + s];
            sL[tid] += sL[tid + s];
            sR[tid] = max(sR[tid], sR[tid + s]);
        }
        __syncthreads();
    }
    if (tid == 0) {
        out[OFF_EM]  = sE[0] / 65536.0f;
        out[OFF_LED] = sL[0] / 65472.0f;
        out[OFF_V]   = (float)sR[0];
    }
}

// ============================================================
extern "C" void kernel_launch(void* const* d_in, const int* in_sizes, int n_in,
                              void* d_out, int out_size) {
    const float* ks = nullptr;
    const float* emb = nullptr;
    const unsigned char* mask = nullptr;
    for (int i = 0; i < n_in; i++) {
        if (in_sizes[i] == ROWS * D_)        ks   = (const float*)d_in[i];
        else if (in_sizes[i] == NCODE * D_)  emb  = (const float*)d_in[i];
        else if (in_sizes[i] == B_)          mask = (const unsigned char*)d_in[i];
    }
    float* out = (float*)d_out;

    cudaFuncSetAttribute(k_gemm_fused,
                         cudaFuncAttributeMaxDynamicSharedMemorySize, SMEM_BYTES);

    {
        int warps = ROWS + NCODE;
        int blocks = (warps * 32 + 255) / 256;
        k_sq<<<blocks, 256>>>(ks, emb);
    }
    k_gemm_fused<<<ROWS / 64, 512, SMEM_BYTES>>>(ks, emb);
    k_scantbl<<<dim3(15, B_), 512>>>();
    k_entries<<<1, 64>>>(mask);
    k_emit_enc<<<dim3(16, B_), 64>>>();
    k_final<<<ROWS / 8, 256>>>(ks, emb, out);
    k_reduce_b<<<B_, 256>>>();
    k_scalars<<<1, 64>>>(out);
}

// round 7
// speedup vs baseline: 1.4362x; 1.2786x over previous
#include <cuda_runtime.h>
#include <cstdint>

typedef unsigned long long ull;

#define B_    64
#define T_    1024
#define D_    128
#define NE    512
#define NCODE 513
#define ROWS  (B_ * T_)   // 65536

// ---- output layout (float32, tuple order) ----
#define OFF_KH  0
#define OFF_ENC 8388608
#define OFF_V   8454144
#define OFF_LH  8454145
#define OFF_LNX 8519681
#define OFF_EM  8585217
#define OFF_LED 8585218

// ---- scratch ----
__device__ float          g_e2[NCODE];
__device__ int            g_minidx[ROWS];
__device__ unsigned       g_move[(size_t)ROWS * 16];
__device__ unsigned short g_tbl[(size_t)B_ * 15 * 512];
__device__ int            g_enc[ROWS];
__device__ float          g_energy[ROWS];
__device__ float          g_pE[B_], g_pL[B_];
__device__ int            g_rng[B_];

// ============================================================
// helpers
// ============================================================
__device__ __forceinline__ uint32_t smem_u32(const void* p) {
    uint32_t a;
    asm("{ .reg .u64 t; cvta.to.shared.u64 t, %1; cvt.u32.u64 %0, t; }"
        : "=r"(a) : "l"(p));
    return a;
}
__device__ __forceinline__ void fma2(ull& d, ull a, ull b) {
    asm("fma.rn.f32x2 %0, %1, %2, %0;" : "+l"(d) : "l"(a), "l"(b));
}
__device__ __forceinline__ ull pack2(float lo, float hi) {
    ull r;
    asm("mov.b64 %0, {%1, %2};" : "=l"(r) : "f"(lo), "f"(hi));
    return r;
}
__device__ __forceinline__ void cpa4(uint32_t dst, const void* src) {
    asm volatile("cp.async.ca.shared.global [%0], [%1], 4;"
                 :: "r"(dst), "l"(src));
}
__device__ __forceinline__ void cpa16(uint32_t dst, const void* src) {
    asm volatile("cp.async.ca.shared.global [%0], [%1], 16;"
                 :: "r"(dst), "l"(src));
}
__device__ __forceinline__ void cpa_commit(void) {
    asm volatile("cp.async.commit_group;");
}
__device__ __forceinline__ void cpa_wait0(void) {
    asm volatile("cp.async.wait_group 0;");
}

// ============================================================
// K0: e2 = row sums of squares of emb (513 rows, warp per row)
// ============================================================
__global__ __launch_bounds__(256) void k_e2(const float* __restrict__ emb) {
    int gw   = (blockIdx.x * 256 + threadIdx.x) >> 5;
    int lane = threadIdx.x & 31;
    if (gw < NCODE) {
        const float4* p = (const float4*)emb + (size_t)gw * 32;
        float4 v = p[lane];
        float s = v.x * v.x;
        s = fmaf(v.y, v.y, s);
        s = fmaf(v.z, v.z, s);
        s = fmaf(v.w, v.w, s);
#pragma unroll
        for (int off = 16; off; off >>= 1) s += __shfl_xor_sync(0xffffffffu, s, off);
        if (lane == 0) g_e2[gw] = s;
    }
}

// ============================================================
// K1: fused FFMA2 GEMM (BM=64, BN=512, K=128), cp.async staging,
//     m-paired f32x2 accumulators + epilogue (argmin + move bits).
// ============================================================
#define E2S_OFF   0
#define AS_OFF    2176                    // 64 rows x 512B = 32KB (full K)
#define BS_OFF    34944                   // 2 buffers x 512 rows x 68B
#define BS_BUF    34816
#define SD_OFF    2176                    // epilogue overlay (As/Bs dead)
#define SD_STRIDE 536
#define SMEM_BYTES 139392

__global__ void __launch_bounds__(512, 1)
k_gemm_fused(const float* __restrict__ A, const float* __restrict__ E) {
    extern __shared__ char smem[];
    float* e2s = (float*)(smem + E2S_OFF);
    const uint32_t sb = smem_u32(smem);
    const int tid = threadIdx.x;
    const int mb  = blockIdx.x;
    const int tx  = tid & 63;
    const int ty  = tid >> 6;

    for (int i = tid; i < NCODE; i += 512) e2s[i] = g_e2[i];

    // ---- A: full 64x128 tile via cp.async.16, row-major ----
#pragma unroll
    for (int i = 0; i < 4; i++) {
        int e = tid + i * 512;            // float4 index, 0..2047
        int kq = e & 31, m = e >> 5;
        cpa16(sb + AS_OFF + (uint32_t)(m * 512 + kq * 16),
              A + (size_t)(mb * 64 + m) * 128 + kq * 4);
    }
    // ---- B chunk 0 via cp.async.4 ----
#pragma unroll
    for (int i = 0; i < 16; i++) {
        int e = tid + i * 512;            // 0..8191
        int kk = e & 15, n = e >> 4;
        cpa4(sb + BS_OFF + (uint32_t)(n * 68 + kk * 4),
             E + (size_t)n * 128 + kk);
    }
    cpa_commit();

    ull acc[32];
#pragma unroll
    for (int i = 0; i < 32; i++) acc[i] = 0ull;

    for (int c = 0; c < 8; c++) {
        cpa_wait0();
        __syncthreads();
        if (c < 7) {
            const int k0 = (c + 1) * 16;
            const uint32_t bbuf = sb + BS_OFF + (uint32_t)(((c + 1) & 1) * BS_BUF);
#pragma unroll
            for (int i = 0; i < 16; i++) {
                int e = tid + i * 512;
                int kk = e & 15, n = e >> 4;
                cpa4(bbuf + (uint32_t)(n * 68 + kk * 4),
                     E + (size_t)n * 128 + k0 + kk);
            }
            cpa_commit();
        }
        const float* Asf = (const float*)(smem + AS_OFF);
        const float* Bsf = (const float*)(smem + BS_OFF + (c & 1) * BS_BUF);
        const int kbase = c * 16;
#pragma unroll 4
        for (int kk = 0; kk < 16; kk++) {
            ull aa[4];
#pragma unroll
            for (int i = 0; i < 4; i++) {
                float ae = Asf[(ty * 8 + 2 * i) * 128 + kbase + kk];
                float ao = Asf[(ty * 8 + 2 * i + 1) * 128 + kbase + kk];
                aa[i] = pack2(ae, ao);
            }
#pragma unroll
            for (int q = 0; q < 8; q++) {
                float b = Bsf[(q * 64 + tx) * 17 + kk];
                ull bb = pack2(b, b);
#pragma unroll
                for (int i = 0; i < 4; i++) fma2(acc[i * 8 + q], aa[i], bb);
            }
        }
        __syncthreads();
    }

    // ---- dump dots to smem d-buffer (overlays As/Bs) ----
    float* sd = (float*)(smem + SD_OFF);
#pragma unroll
    for (int i = 0; i < 4; i++) {
        int m0 = ty * 8 + 2 * i;
#pragma unroll
        for (int q = 0; q < 8; q++) {
            ull v = acc[i * 8 + q];
            sd[(size_t)m0 * SD_STRIDE + q * 64 + tx] =
                __uint_as_float((unsigned)v);
            sd[(size_t)(m0 + 1) * SD_STRIDE + q * 64 + tx] =
                __uint_as_float((unsigned)(v >> 32));
        }
    }
    __syncthreads();

    // ---- row scan: 8 threads per row, strided cols ----
    const int t   = tid & 7;
    const int rid = tid >> 3;
    const int row_g = mb * 64 + rid;

    // ks2 + dot with code 512
    float ks2 = 0.0f, dt = 0.0f;
    {
        const float4* kr = (const float4*)A + (size_t)row_g * 32;
        const float4* er = (const float4*)E + (size_t)512 * 32;
#pragma unroll
        for (int j = 0; j < 4; j++) {
            float4 a = kr[t * 4 + j];
            float4 e = __ldg(&er[t * 4 + j]);
            ks2 = fmaf(a.x, a.x, ks2); ks2 = fmaf(a.y, a.y, ks2);
            ks2 = fmaf(a.z, a.z, ks2); ks2 = fmaf(a.w, a.w, ks2);
            dt  = fmaf(a.x, e.x, dt);  dt  = fmaf(a.y, e.y, dt);
            dt  = fmaf(a.z, e.z, dt);  dt  = fmaf(a.w, e.w, dt);
        }
#pragma unroll
        for (int o = 1; o < 8; o <<= 1) {
            ks2 += __shfl_xor_sync(0xffffffffu, ks2, o);
            dt  += __shfl_xor_sync(0xffffffffu, dt, o);
        }
    }
    float d512 = (ks2 + e2s[512]) - 2.0f * dt;

    const float* sdr = sd + (size_t)rid * SD_STRIDE;
    float best = 3.4e38f;
    int   bi = 0;
    float dprev = 0.0f;
    unsigned word = 0;
    const unsigned shift = (unsigned)(tid & 24);  // 8 * (lane group)
#pragma unroll 4
    for (int k = 0; k < 64; k++) {
        float d = (ks2 + e2s[8 * k + t]) - 2.0f * sdr[8 * k + t];
        if (k > 0) {
            float dnb = __shfl_down_sync(0xffffffffu, dprev, 1, 8);
            float d0  = __shfl_sync(0xffffffffu, d, 0, 8);
            float nxt = (t == 7) ? d0 : dnb;
            unsigned Bb = __ballot_sync(0xffffffffu, dprev > nxt);
            word |= ((Bb >> shift) & 0xFFu) << (((k - 1) & 3) * 8);
            if (((k - 1) & 3) == 3) {
                if (t == 0) g_move[(size_t)row_g * 16 + ((k - 1) >> 2)] = word;
                word = 0;
            }
        }
        if (d < best) { best = d; bi = 8 * k + t; }
        dprev = d;
    }
    {
        float dnb = __shfl_down_sync(0xffffffffu, dprev, 1, 8);
        unsigned Bb = __ballot_sync(0xffffffffu, (t < 7) && (dprev > dnb));
        word |= ((Bb >> shift) & 0xFFu) << 24;
        if (t == 0) g_move[(size_t)row_g * 16 + 15] = word;
    }
#pragma unroll
    for (int o = 1; o < 8; o <<= 1) {
        float ov = __shfl_xor_sync(0xffffffffu, best, o);
        int   oi = __shfl_xor_sync(0xffffffffu, bi, o);
        if (ov < best || (ov == best && oi < bi)) { best = ov; bi = oi; }
    }
    if (d512 < best) bi = 512;
    if (t == 0) g_minidx[row_g] = bi;
}

// ============================================================
// K3a: chunk transition tables
// ============================================================
__global__ __launch_bounds__(512) void k_scantbl(void) {
    const int c   = blockIdx.x;     // 0..14
    const int b   = blockIdx.y;
    const int tid = threadIdx.x;
    __shared__ unsigned mw[64][16];
    const int t0 = c * 64 + 1;
#pragma unroll
    for (int r = 0; r < 2; r++) {
        int i = tid + r * 512;
        mw[i >> 4][i & 15] =
            g_move[(size_t)(b * 1024 + t0 + (i >> 4)) * 16 + (i & 15)];
    }
    __syncthreads();
    int ind = tid;
    for (int s = 0; s < 64; s++) ind += (mw[s][ind >> 5] >> (ind & 31)) & 1;
    g_tbl[((size_t)b * 15 + c) * 512 + tid] = (unsigned short)ind;
}

// ============================================================
// K3c: compute chunk entry state in-block (walk <=15 tables),
//      then re-simulate within chunk, emit enc. (k_entries fused in)
// ============================================================
__global__ __launch_bounds__(64) void k_emit_enc(const unsigned char* __restrict__ mask) {
    const int c   = blockIdx.x;     // 0..15
    const int b   = blockIdx.y;
    const int tid = threadIdx.x;
    __shared__ unsigned mw[63][16];
    __shared__ int s_ent;
    const int t0 = c * 64 + 1;
    for (int i = tid; i < 63 * 16; i += 64)
        mw[i >> 4][i & 15] =
            g_move[(size_t)(b * 1024 + t0 + (i >> 4)) * 16 + (i & 15)];
    if (tid == 0) {
        int ind = g_minidx[b * 1024];
        if (ind > 511) ind = 511;
        if (mask[b]) ind = 0;
        for (int cc = 0; cc < c; cc++)
            ind = g_tbl[((size_t)b * 15 + cc) * 512 + ind];
        s_ent = ind;
    }
    __syncthreads();
    int ind = s_ent;
    for (int s = 0; s < tid; s++) ind += (mw[s][ind >> 5] >> (ind & 31)) & 1;
    g_enc[b * 1024 + c * 64 + tid] = ind;
}

// ============================================================
// K4: fused gathers + losses + key_hard + energy. Warp per (b,t).
// ============================================================
__global__ __launch_bounds__(256) void k_final(const float* __restrict__ ks,
                                               const float* __restrict__ emb,
                                               float* __restrict__ out) {
    const int row  = blockIdx.x * 8 + (threadIdx.x >> 5);
    const int lane = threadIdx.x & 31;
    const float4* k4 = (const float4*)ks + (size_t)row * 32;
    const float4* e4 = (const float4*)emb;

    int here = g_enc[row];
    int nxt  = here + 1; if (nxt > 511) nxt = 511;
    int mi   = g_minidx[row];

    float4 a  = k4[lane];
    float4 eh = e4[(size_t)here * 32 + lane];
    float4 en = e4[(size_t)nxt * 32 + lane];
    float4 em = e4[(size_t)mi * 32 + lane];

    float sh, sn, sm;
    {
        float d0 = a.x - eh.x, d1 = a.y - eh.y, d2 = a.z - eh.z, d3 = a.w - eh.w;
        sh = d0 * d0; sh = fmaf(d1, d1, sh); sh = fmaf(d2, d2, sh); sh = fmaf(d3, d3, sh);
    }
    {
        float d0 = a.x - en.x, d1 = a.y - en.y, d2 = a.z - en.z, d3 = a.w - en.w;
        sn = d0 * d0; sn = fmaf(d1, d1, sn); sn = fmaf(d2, d2, sn); sn = fmaf(d3, d3, sn);
    }
    {
        float d0 = a.x - em.x, d1 = a.y - em.y, d2 = a.z - em.z, d3 = a.w - em.w;
        sm = d0 * d0; sm = fmaf(d1, d1, sm); sm = fmaf(d2, d2, sm); sm = fmaf(d3, d3, sm);
    }
#pragma unroll
    for (int off = 16; off; off >>= 1) {
        sh += __shfl_xor_sync(0xffffffffu, sh, off);
        sn += __shfl_xor_sync(0xffffffffu, sn, off);
        sm += __shfl_xor_sync(0xffffffffu, sm, off);
    }

    float4 o;
    o.x = a.x + (eh.x - a.x);
    o.y = a.y + (eh.y - a.y);
    o.z = a.z + (eh.z - a.z);
    o.w = a.w + (eh.w - a.w);
    ((float4*)(out + OFF_KH))[(size_t)row * 32 + lane] = o;

    if (lane == 0) {
        float Lh = sh + sh * 0.2f;
        float Ln = sn + sn * 0.2f;
        float Lm = sm + sm * 0.2f;
        float dif = sn - sh;
        float energy = dif + dif * 0.2f;
        float lmh = (Lm < Lh) ? Lm : 0.0f;
        float lmn = (Lm < Ln) ? Lm : 0.0f;
        out[OFF_LH  + row] = (Lh - Ln) - lmh;
        out[OFF_LNX + row] = (Ln - Lh) - lmn;
        out[OFF_ENC + row] = (float)here;
        g_energy[row] = energy;
    }
}

// ============================================================
// K5: per-batch reductions
// ============================================================
__global__ __launch_bounds__(256) void k_reduce_b(void) {
    const int b   = blockIdx.x;
    const int tid = threadIdx.x;
    __shared__ float sE[256], sL[256];
    __shared__ int   sMn[256], sMx[256];
    const float* eb = g_energy + b * 1024;
    const int*   cb = g_enc + b * 1024;

    float aE = 0.0f, aL = 0.0f;
    int mn = 1 << 30, mx = -1;
    for (int t = tid; t < 1024; t += 256) {
        aE += eb[t];
        int cv = cb[t];
        mn = min(mn, cv);
        mx = max(mx, cv);
    }
    const float EPS = (float)(1e-6 / 512.0);
    for (int t = tid + 1; t < 1024; t += 256) {
        float ch = (cb[t] != cb[t - 1]) ? 0.0f : (eb[t] - eb[t - 1]);
        aL += fmaxf(ch + EPS, 0.0f);
    }
    sE[tid] = aE; sL[tid] = aL; sMn[tid] = mn; sMx[tid] = mx;
    __syncthreads();
    for (int s = 128; s; s >>= 1) {
        if (tid < s) {
            sE[tid] += sE[tid + s];
            sL[tid] += sL[tid + s];
            sMn[tid] = min(sMn[tid], sMn[tid + s]);
            sMx[tid] = max(sMx[tid], sMx[tid + s]);
        }
        __syncthreads();
    }
    if (tid == 0) {
        g_pE[b]  = sE[0];
        g_pL[b]  = sL[0];
        g_rng[b] = sMx[0] - sMn[0];
    }
}

// ============================================================
// K6: final scalars
// ============================================================
__global__ void k_scalars(float* __restrict__ out) {
    int tid = threadIdx.x;  // 64
    __shared__ float sE[64], sL[64];
    __shared__ int   sR[64];
    sE[tid] = g_pE[tid]; sL[tid] = g_pL[tid]; sR[tid] = g_rng[tid];
    __syncthreads();
    for (int s = 32; s; s >>= 1) {
        if (tid < s) {
            sE[tid] += sE[tid + s];
            sL[tid] += sL[tid + s];
            sR[tid] = max(sR[tid], sR[tid + s]);
        }
        __syncthreads();
    }
    if (tid == 0) {
        out[OFF_EM]  = sE[0] / 65536.0f;
        out[OFF_LED] = sL[0] / 65472.0f;
        out[OFF_V]   = (float)sR[0];
    }
}

// ============================================================
extern "C" void kernel_launch(void* const* d_in, const int* in_sizes, int n_in,
                              void* d_out, int out_size) {
    const float* ks = nullptr;
    const float* emb = nullptr;
    const unsigned char* mask = nullptr;
    for (int i = 0; i < n_in; i++) {
        if (in_sizes[i] == ROWS * D_)        ks   = (const float*)d_in[i];
        else if (in_sizes[i] == NCODE * D_)  emb  = (const float*)d_in[i];
        else if (in_sizes[i] == B_)          mask = (const unsigned char*)d_in[i];
    }
    float* out = (float*)d_out;

    cudaFuncSetAttribute(k_gemm_fused,
                         cudaFuncAttributeMaxDynamicSharedMemorySize, SMEM_BYTES);

    k_e2<<<(NCODE * 32 + 255) / 256, 256>>>(emb);
    k_gemm_fused<<<ROWS / 64, 512, SMEM_BYTES>>>(ks, emb);
    k_scantbl<<<dim3(15, B_), 512>>>();
    k_emit_enc<<<dim3(16, B_), 64>>>(mask);
    k_final<<<ROWS / 8, 256>>>(ks, emb, out);
    k_reduce_b<<<B_, 256>>>();
    k_scalars<<<1, 64>>>(out);
}

// round 10
// speedup vs baseline: 1.9334x; 1.3462x over previous
#include <cuda_runtime.h>
#include <cstdint>

typedef unsigned long long ull;

#define B_    64
#define T_    1024
#define D_    128
#define NE    512
#define NCODE 513
#define ROWS  (B_ * T_)   // 65536

// ---- output layout (float32, tuple order) ----
#define OFF_KH  0
#define OFF_ENC 8388608
#define OFF_V   8454144
#define OFF_LH  8454145
#define OFF_LNX 8519681
#define OFF_EM  8585217
#define OFF_LED 8585218

// ---- scratch ----
__device__ float          g_Ah[(size_t)ROWS * D_];   // tf32 hi of key_soft
__device__ float          g_Al[(size_t)ROWS * D_];   // tf32 lo
__device__ float          g_Bht[(size_t)D_ * NE];    // tf32 hi of emb^T [k][n]
__device__ float          g_Blt[(size_t)D_ * NE];    // tf32 lo
__device__ float          g_e2[NCODE];
__device__ int            g_minidx[ROWS];
__device__ unsigned       g_move[(size_t)ROWS * 16];
__device__ unsigned short g_tbl[(size_t)B_ * 15 * 512];
__device__ int            g_enc[ROWS];
__device__ float          g_energy[ROWS];
__device__ float          g_pE[B_], g_pL[B_];
__device__ int            g_rng[B_];

// ============================================================
// helpers
// ============================================================
__device__ __forceinline__ uint32_t smem_u32(const void* p) {
    uint32_t a;
    asm("{ .reg .u64 t; cvta.to.shared.u64 t, %1; cvt.u32.u64 %0, t; }"
        : "=r"(a) : "l"(p));
    return a;
}
__device__ __forceinline__ float cvt_tf32f(float x) {
    uint32_t u;
    asm("cvt.rna.tf32.f32 %0, %1;" : "=r"(u) : "f"(x));
    return __uint_as_float(u);
}
__device__ __forceinline__ void cpa16(uint32_t dst, const void* src) {
    asm volatile("cp.async.ca.shared.global [%0], [%1], 16;"
                 :: "r"(dst), "l"(src));
}
__device__ __forceinline__ void cpa_commit(void) {
    asm volatile("cp.async.commit_group;");
}
__device__ __forceinline__ void cpa_wait0(void) {
    asm volatile("cp.async.wait_group 0;");
}
__device__ __forceinline__ void mma8(float* d, const unsigned* a,
                                     unsigned b0, unsigned b1) {
    asm("mma.sync.aligned.m16n8k8.row.col.f32.tf32.tf32.f32 "
        "{%0,%1,%2,%3}, {%4,%5,%6,%7}, {%8,%9}, {%0,%1,%2,%3};"
        : "+f"(d[0]), "+f"(d[1]), "+f"(d[2]), "+f"(d[3])
        : "r"(a[0]), "r"(a[1]), "r"(a[2]), "r"(a[3]), "r"(b0), "r"(b1));
}

// ============================================================
// K-1a: split A into tf32 hi/lo (elementwise, float4)
// ============================================================
__global__ __launch_bounds__(256) void k_split_a(const float* __restrict__ A) {
    size_t idx = (size_t)blockIdx.x * 256 + threadIdx.x;   // float4 granularity
    float4 v = ((const float4*)A)[idx];
    float4 h, l;
    h.x = cvt_tf32f(v.x); l.x = cvt_tf32f(v.x - h.x);
    h.y = cvt_tf32f(v.y); l.y = cvt_tf32f(v.y - h.y);
    h.z = cvt_tf32f(v.z); l.z = cvt_tf32f(v.z - h.z);
    h.w = cvt_tf32f(v.w); l.w = cvt_tf32f(v.w - h.w);
    ((float4*)g_Ah)[idx] = h;
    ((float4*)g_Al)[idx] = l;
}

// ============================================================
// K-1b: per-row e2 for all 513 codes + transposed tf32 split of
//       emb rows 0..511 into Bht/Blt [k][n]. Warp per row.
// ============================================================
__global__ __launch_bounds__(256) void k_split_b(const float* __restrict__ emb) {
    int gw   = (blockIdx.x * 256 + threadIdx.x) >> 5;
    int lane = threadIdx.x & 31;
    if (gw >= NCODE) return;
    float4 v = ((const float4*)emb)[(size_t)gw * 32 + lane];
    float s = v.x * v.x;
    s = fmaf(v.y, v.y, s);
    s = fmaf(v.z, v.z, s);
    s = fmaf(v.w, v.w, s);
#pragma unroll
    for (int off = 16; off; off >>= 1) s += __shfl_xor_sync(0xffffffffu, s, off);
    if (lane == 0) g_e2[gw] = s;
    if (gw < NE) {
        const float* vp = &v.x;
#pragma unroll
        for (int q = 0; q < 4; q++) {
            int k = lane * 4 + q;
            float h = cvt_tf32f(vp[q]);
            float l = cvt_tf32f(vp[q] - h);
            g_Bht[(size_t)k * NE + gw] = h;
            g_Blt[(size_t)k * NE + gw] = l;
        }
    }
}

// ============================================================
// K1: fused mma.sync tf32 3-pass GEMM (BM=64, BN=512, K=128)
//     + epilogue (d assembly, argmin over 513, move bits).
// ============================================================
#define E2S_OFF    0
#define AS_OFF     2176        // 2 buf x (hi 5120B + lo 5120B) = 20480
#define ABUF_STR   10240
#define ALO_OFF    5120
#define BS_OFF     22656       // 2 buf x (hi 33280B + lo 33280B) = 133120
#define BBUF_STR   66560
#define BLO_OFF    33280
#define SD_OFF     2176        // epilogue overlay
#define SD_STRIDE  536
#define SMEM_BYTES 155776

__global__ void __launch_bounds__(512, 1)
k_gemm_fused(const float* __restrict__ A, const float* __restrict__ E) {
    extern __shared__ char smem[];
    float* e2s = (float*)(smem + E2S_OFF);
    const uint32_t sb = smem_u32(smem);
    const int tid  = threadIdx.x;
    const int mb   = blockIdx.x;
    const int wid  = tid >> 5;
    const int lane = tid & 31;
    const int wm   = wid & 3;        // m strip (16 rows)
    const int wn   = wid >> 2;       // n strip (128 cols)
    const int g    = lane >> 2;      // group id 0..7
    const int cc   = lane & 3;       // thread in group

    for (int i = tid; i < NCODE; i += 512) e2s[i] = g_e2[i];

    // ---- staging lambdas (chunk = 16 k-columns) ----
    auto stage = [&](int c, int buf) {
        const int k0 = c * 16;
        // A: hi/lo 64 rows x 16 cols, 4 float4 per row; 512 cpa16 total
        {
            int part = tid >> 8;           // 0 hi, 1 lo
            int r = tid & 255;
            int m = r >> 2, q = r & 3;
            const float* src = (part ? g_Al : g_Ah) +
                               (size_t)(mb * 64 + m) * 128 + k0 + q * 4;
            cpa16(sb + AS_OFF + buf * ABUF_STR + part * ALO_OFF +
                      (uint32_t)(m * 80 + q * 16), src);
        }
        // B: hi/lo 16 k-rows x 512 n; 4096 cpa16 total -> 8 per thread
#pragma unroll
        for (int i = 0; i < 8; i++) {
            int e = tid + i * 512;
            int part = e >> 11;
            int r = e & 2047;
            int k = r >> 7, n4 = r & 127;
            const float* src = (part ? g_Blt : g_Bht) +
                               (size_t)(k0 + k) * NE + n4 * 4;
            cpa16(sb + BS_OFF + buf * BBUF_STR + part * BLO_OFF +
                      (uint32_t)(k * 2080 + n4 * 16), src);
        }
        cpa_commit();
    };

    float acc[16][4];
#pragma unroll
    for (int i = 0; i < 16; i++)
#pragma unroll
        for (int j = 0; j < 4; j++) acc[i][j] = 0.0f;

    stage(0, 0);
    for (int c = 0; c < 8; c++) {
        cpa_wait0();
        __syncthreads();
        if (c < 7) stage(c + 1, (c + 1) & 1);

        const float* Af = (const float*)(smem + AS_OFF + (c & 1) * ABUF_STR);
        const float* Bf = (const float*)(smem + BS_OFF + (c & 1) * BBUF_STR);
        const float* Alf = Af + 1280;    // ALO_OFF bytes = 1280 floats
        const float* Blf = Bf + 8320;    // BLO_OFF bytes = 8320 floats

#pragma unroll
        for (int k8 = 0; k8 < 2; k8++) {
            const int kb = k8 * 8;
            unsigned ah[4], al[4];
            const int ab = (wm * 16 + g) * 20 + kb + cc;
            ah[0] = __float_as_uint(Af[ab]);
            ah[1] = __float_as_uint(Af[ab + 160]);
            ah[2] = __float_as_uint(Af[ab + 4]);
            ah[3] = __float_as_uint(Af[ab + 164]);
            al[0] = __float_as_uint(Alf[ab]);
            al[1] = __float_as_uint(Alf[ab + 160]);
            al[2] = __float_as_uint(Alf[ab + 4]);
            al[3] = __float_as_uint(Alf[ab + 164]);
#pragma unroll
            for (int nb = 0; nb < 16; nb++) {
                const int bb = (kb + cc) * 520 + wn * 128 + nb * 8 + g;
                unsigned bh0 = __float_as_uint(Bf[bb]);
                unsigned bh1 = __float_as_uint(Bf[bb + 2080]);
                unsigned bl0 = __float_as_uint(Blf[bb]);
                unsigned bl1 = __float_as_uint(Blf[bb + 2080]);
                mma8(acc[nb], ah, bh0, bh1);
                mma8(acc[nb], ah, bl0, bl1);
                mma8(acc[nb], al, bh0, bh1);
            }
        }
        __syncthreads();
    }

    // ---- dump acc fragments to smem d-buffer (overlays tiles) ----
    float* sd = (float*)(smem + SD_OFF);
    {
        const int row0 = wm * 16 + g;
#pragma unroll
        for (int nb = 0; nb < 16; nb++) {
            const int col = wn * 128 + nb * 8 + 2 * cc;
            *(float2*)&sd[(size_t)row0 * SD_STRIDE + col] =
                make_float2(acc[nb][0], acc[nb][1]);
            *(float2*)&sd[(size_t)(row0 + 8) * SD_STRIDE + col] =
                make_float2(acc[nb][2], acc[nb][3]);
        }
    }
    __syncthreads();

    // ---- row scan: 8 threads per row, strided cols ----
    const int t   = tid & 7;
    const int rid = tid >> 3;
    const int row_g = mb * 64 + rid;

    // ks2 + dot with code 512 (fp32 from original inputs)
    float ks2 = 0.0f, dt = 0.0f;
    {
        const float4* kr = (const float4*)A + (size_t)row_g * 32;
        const float4* er = (const float4*)E + (size_t)512 * 32;
#pragma unroll
        for (int j = 0; j < 4; j++) {
            float4 a = kr[t * 4 + j];
            float4 e = __ldg(&er[t * 4 + j]);
            ks2 = fmaf(a.x, a.x, ks2); ks2 = fmaf(a.y, a.y, ks2);
            ks2 = fmaf(a.z, a.z, ks2); ks2 = fmaf(a.w, a.w, ks2);
            dt  = fmaf(a.x, e.x, dt);  dt  = fmaf(a.y, e.y, dt);
            dt  = fmaf(a.z, e.z, dt);  dt  = fmaf(a.w, e.w, dt);
        }
#pragma unroll
        for (int o = 1; o < 8; o <<= 1) {
            ks2 += __shfl_xor_sync(0xffffffffu, ks2, o);
            dt  += __shfl_xor_sync(0xffffffffu, dt, o);
        }
    }
    float d512 = (ks2 + e2s[512]) - 2.0f * dt;

    const float* sdr = sd + (size_t)rid * SD_STRIDE;
    float best = 3.4e38f;
    int   bi = 0;
    float dprev = 0.0f;
    unsigned word = 0;
    const unsigned shift = (unsigned)(tid & 24);  // 8 * (lane group)
#pragma unroll 4
    for (int k = 0; k < 64; k++) {
        float d = (ks2 + e2s[8 * k + t]) - 2.0f * sdr[8 * k + t];
        if (k > 0) {
            float dnb = __shfl_down_sync(0xffffffffu, dprev, 1, 8);
            float d0  = __shfl_sync(0xffffffffu, d, 0, 8);
            float nxt = (t == 7) ? d0 : dnb;
            unsigned Bb = __ballot_sync(0xffffffffu, dprev > nxt);
            word |= ((Bb >> shift) & 0xFFu) << (((k - 1) & 3) * 8);
            if (((k - 1) & 3) == 3) {
                if (t == 0) g_move[(size_t)row_g * 16 + ((k - 1) >> 2)] = word;
                word = 0;
            }
        }
        if (d < best) { best = d; bi = 8 * k + t; }
        dprev = d;
    }
    {
        float dnb = __shfl_down_sync(0xffffffffu, dprev, 1, 8);
        unsigned Bb = __ballot_sync(0xffffffffu, (t < 7) && (dprev > dnb));
        word |= ((Bb >> shift) & 0xFFu) << 24;
        if (t == 0) g_move[(size_t)row_g * 16 + 15] = word;
    }
#pragma unroll
    for (int o = 1; o < 8; o <<= 1) {
        float ov = __shfl_xor_sync(0xffffffffu, best, o);
        int   oi = __shfl_xor_sync(0xffffffffu, bi, o);
        if (ov < best || (ov == best && oi < bi)) { best = ov; bi = oi; }
    }
    if (d512 < best) bi = 512;
    if (t == 0) g_minidx[row_g] = bi;
}

// ============================================================
// K3a: chunk transition tables
// ============================================================
__global__ __launch_bounds__(512) void k_scantbl(void) {
    const int c   = blockIdx.x;     // 0..14
    const int b   = blockIdx.y;
    const int tid = threadIdx.x;
    __shared__ unsigned mw[64][16];
    const int t0 = c * 64 + 1;
#pragma unroll
    for (int r = 0; r < 2; r++) {
        int i = tid + r * 512;
        mw[i >> 4][i & 15] =
            g_move[(size_t)(b * 1024 + t0 + (i >> 4)) * 16 + (i & 15)];
    }
    __syncthreads();
    int ind = tid;
    for (int s = 0; s < 64; s++) ind += (mw[s][ind >> 5] >> (ind & 31)) & 1;
    g_tbl[((size_t)b * 15 + c) * 512 + tid] = (unsigned short)ind;
}

// ============================================================
// K3c: compute chunk entry state in-block, re-simulate, emit enc
// ============================================================
__global__ __launch_bounds__(64) void k_emit_enc(const unsigned char* __restrict__ mask) {
    const int c   = blockIdx.x;     // 0..15
    const int b   = blockIdx.y;
    const int tid = threadIdx.x;
    __shared__ unsigned mw[63][16];
    __shared__ int s_ent;
    const int t0 = c * 64 + 1;
    for (int i = tid; i < 63 * 16; i += 64)
        mw[i >> 4][i & 15] =
            g_move[(size_t)(b * 1024 + t0 + (i >> 4)) * 16 + (i & 15)];
    if (tid == 0) {
        int ind = g_minidx[b * 1024];
        if (ind > 511) ind = 511;
        if (mask[b]) ind = 0;
        for (int cc = 0; cc < c; cc++)
            ind = g_tbl[((size_t)b * 15 + cc) * 512 + ind];
        s_ent = ind;
    }
    __syncthreads();
    int ind = s_ent;
    for (int s = 0; s < tid; s++) ind += (mw[s][ind >> 5] >> (ind & 31)) & 1;
    g_enc[b * 1024 + c * 64 + tid] = ind;
}

// ============================================================
// K4: fused gathers + losses + key_hard + energy. Warp per (b,t).
// ============================================================
__global__ __launch_bounds__(256) void k_final(const float* __restrict__ ks,
                                               const float* __restrict__ emb,
                                               float* __restrict__ out) {
    const int row  = blockIdx.x * 8 + (threadIdx.x >> 5);
    const int lane = threadIdx.x & 31;
    const float4* k4 = (const float4*)ks + (size_t)row * 32;
    const float4* e4 = (const float4*)emb;

    int here = g_enc[row];
    int nxt  = here + 1; if (nxt > 511) nxt = 511;
    int mi   = g_minidx[row];

    float4 a  = k4[lane];
    float4 eh = e4[(size_t)here * 32 + lane];
    float4 en = e4[(size_t)nxt * 32 + lane];
    float4 em = e4[(size_t)mi * 32 + lane];

    float sh, sn, sm;
    {
        float d0 = a.x - eh.x, d1 = a.y - eh.y, d2 = a.z - eh.z, d3 = a.w - eh.w;
        sh = d0 * d0; sh = fmaf(d1, d1, sh); sh = fmaf(d2, d2, sh); sh = fmaf(d3, d3, sh);
    }
    {
        float d0 = a.x - en.x, d1 = a.y - en.y, d2 = a.z - en.z, d3 = a.w - en.w;
        sn = d0 * d0; sn = fmaf(d1, d1, sn); sn = fmaf(d2, d2, sn); sn = fmaf(d3, d3, sn);
    }
    {
        float d0 = a.x - em.x, d1 = a.y - em.y, d2 = a.z - em.z, d3 = a.w - em.w;
        sm = d0 * d0; sm = fmaf(d1, d1, sm); sm = fmaf(d2, d2, sm); sm = fmaf(d3, d3, sm);
    }
#pragma unroll
    for (int off = 16; off; off >>= 1) {
        sh += __shfl_xor_sync(0xffffffffu, sh, off);
        sn += __shfl_xor_sync(0xffffffffu, sn, off);
        sm += __shfl_xor_sync(0xffffffffu, sm, off);
    }

    float4 o;
    o.x = a.x + (eh.x - a.x);
    o.y = a.y + (eh.y - a.y);
    o.z = a.z + (eh.z - a.z);
    o.w = a.w + (eh.w - a.w);
    ((float4*)(out + OFF_KH))[(size_t)row * 32 + lane] = o;

    if (lane == 0) {
        float Lh = sh + sh * 0.2f;
        float Ln = sn + sn * 0.2f;
        float Lm = sm + sm * 0.2f;
        float dif = sn - sh;
        float energy = dif + dif * 0.2f;
        float lmh = (Lm < Lh) ? Lm : 0.0f;
        float lmn = (Lm < Ln) ? Lm : 0.0f;
        out[OFF_LH  + row] = (Lh - Ln) - lmh;
        out[OFF_LNX + row] = (Ln - Lh) - lmn;
        out[OFF_ENC + row] = (float)here;
        g_energy[row] = energy;
    }
}

// ============================================================
// K5: per-batch reductions
// ============================================================
__global__ __launch_bounds__(256) void k_reduce_b(void) {
    const int b   = blockIdx.x;
    const int tid = threadIdx.x;
    __shared__ float sE[256], sL[256];
    __shared__ int   sMn[256], sMx[256];
    const float* eb = g_energy + b * 1024;
    const int*   cb = g_enc + b * 1024;

    float aE = 0.0f, aL = 0.0f;
    int mn = 1 << 30, mx = -1;
    for (int t = tid; t < 1024; t += 256) {
        aE += eb[t];
        int cv = cb[t];
        mn = min(mn, cv);
        mx = max(mx, cv);
    }
    const float EPS = (float)(1e-6 / 512.0);
    for (int t = tid + 1; t < 1024; t += 256) {
        float ch = (cb[t] != cb[t - 1]) ? 0.0f : (eb[t] - eb[t - 1]);
        aL += fmaxf(ch + EPS, 0.0f);
    }
    sE[tid] = aE; sL[tid] = aL; sMn[tid] = mn; sMx[tid] = mx;
    __syncthreads();
    for (int s = 128; s; s >>= 1) {
        if (tid < s) {
            sE[tid] += sE[tid + s];
            sL[tid] += sL[tid + s];
            sMn[tid] = min(sMn[tid], sMn[tid + s]);
            sMx[tid] = max(sMx[tid], sMx[tid + s]);
        }
        __syncthreads();
    }
    if (tid == 0) {
        g_pE[b]  = sE[0];
        g_pL[b]  = sL[0];
        g_rng[b] = sMx[0] - sMn[0];
    }
}

// ============================================================
// K6: final scalars
// ============================================================
__global__ void k_scalars(float* __restrict__ out) {
    int tid = threadIdx.x;  // 64
    __shared__ float sE[64], sL[64];
    __shared__ int   sR[64];
    sE[tid] = g_pE[tid]; sL[tid] = g_pL[tid]; sR[tid] = g_rng[tid];
    __syncthreads();
    for (int s = 32; s; s >>= 1) {
        if (tid < s) {
            sE[tid] += sE[tid + s];
            sL[tid] += sL[tid + s];
            sR[tid] = max(sR[tid], sR[tid + s]);
        }
        __syncthreads();
    }
    if (tid == 0) {
        out[OFF_EM]  = sE[0] / 65536.0f;
        out[OFF_LED] = sL[0] / 65472.0f;
        out[OFF_V]   = (float)sR[0];
    }
}

// ============================================================
extern "C" void kernel_launch(void* const* d_in, const int* in_sizes, int n_in,
                              void* d_out, int out_size) {
    const float* ks = nullptr;
    const float* emb = nullptr;
    const unsigned char* mask = nullptr;
    for (int i = 0; i < n_in; i++) {
        if (in_sizes[i] == ROWS * D_)        ks   = (const float*)d_in[i];
        else if (in_sizes[i] == NCODE * D_)  emb  = (const float*)d_in[i];
        else if (in_sizes[i] == B_)          mask = (const unsigned char*)d_in[i];
    }
    float* out = (float*)d_out;

    cudaFuncSetAttribute(k_gemm_fused,
                         cudaFuncAttributeMaxDynamicSharedMemorySize, SMEM_BYTES);

    k_split_a<<<ROWS * D_ / 4 / 256, 256>>>(ks);
    k_split_b<<<(NCODE * 32 + 255) / 256, 256>>>(emb);
    k_gemm_fused<<<ROWS / 64, 512, SMEM_BYTES>>>(ks, emb);
    k_scantbl<<<dim3(15, B_), 512>>>();
    k_emit_enc<<<dim3(16, B_), 64>>>(mask);
    k_final<<<ROWS / 8, 256>>>(ks, emb, out);
    k_reduce_b<<<B_, 256>>>();
    k_scalars<<<1, 64>>>(out);
}

// round 11
// speedup vs baseline: 2.3729x; 1.2273x over previous
#include <cuda_runtime.h>
#include <cuda_fp16.h>
#include <cstdint>

typedef unsigned long long ull;

#define B_    64
#define T_    1024
#define D_    128
#define NE    512
#define NCODE 513
#define ROWS  (B_ * T_)   // 65536

// ---- output layout (float32, tuple order) ----
#define OFF_KH  0
#define OFF_ENC 8388608
#define OFF_V   8454144
#define OFF_LH  8454145
#define OFF_LNX 8519681
#define OFF_EM  8585217
#define OFF_LED 8585218

// ---- scratch ----
__device__ __half         g_A0[(size_t)ROWS * D_];   // fp16 hi limb of key_soft
__device__ __half         g_A1[(size_t)ROWS * D_];   // fp16 lo limb
__device__ __half         g_B0[(size_t)NE * D_];     // fp16 hi limb of 512*emb [n][k]
__device__ __half         g_B1[(size_t)NE * D_];     // fp16 lo limb
__device__ float          g_e2[NCODE];
__device__ int            g_minidx[ROWS];
__device__ unsigned       g_move[(size_t)ROWS * 16];
__device__ unsigned short g_tbl[(size_t)B_ * 15 * 512];
__device__ int            g_enc[ROWS];
__device__ float          g_energy[ROWS];
__device__ float          g_pE[B_], g_pL[B_];
__device__ int            g_rng[B_];

// ============================================================
// helpers
// ============================================================
__device__ __forceinline__ uint32_t smem_u32(const void* p) {
    uint32_t a;
    asm("{ .reg .u64 t; cvta.to.shared.u64 t, %1; cvt.u32.u64 %0, t; }"
        : "=r"(a) : "l"(p));
    return a;
}
__device__ __forceinline__ void cpa16(uint32_t dst, const void* src) {
    asm volatile("cp.async.ca.shared.global [%0], [%1], 16;"
                 :: "r"(dst), "l"(src));
}
__device__ __forceinline__ void cpa_commit(void) {
    asm volatile("cp.async.commit_group;");
}
__device__ __forceinline__ void cpa_wait0(void) {
    asm volatile("cp.async.wait_group 0;");
}
__device__ __forceinline__ void mma16(float* d, const unsigned* a,
                                      unsigned b0, unsigned b1) {
    asm("mma.sync.aligned.m16n8k16.row.col.f32.f16.f16.f32 "
        "{%0,%1,%2,%3}, {%4,%5,%6,%7}, {%8,%9}, {%0,%1,%2,%3};"
        : "+f"(d[0]), "+f"(d[1]), "+f"(d[2]), "+f"(d[3])
        : "r"(a[0]), "r"(a[1]), "r"(a[2]), "r"(a[3]), "r"(b0), "r"(b1));
}

// ============================================================
// K-1a: split A into fp16 hi/lo limbs (elementwise, float4 in, 2x half2 out)
// ============================================================
__global__ __launch_bounds__(256) void k_split_a(const float* __restrict__ A) {
    size_t idx = (size_t)blockIdx.x * 256 + threadIdx.x;   // float4 granularity
    float4 v = ((const float4*)A)[idx];
    __half h0x = __float2half_rn(v.x), h0y = __float2half_rn(v.y);
    __half h0z = __float2half_rn(v.z), h0w = __float2half_rn(v.w);
    __half l0x = __float2half_rn(v.x - __half2float(h0x));
    __half l0y = __float2half_rn(v.y - __half2float(h0y));
    __half l0z = __float2half_rn(v.z - __half2float(h0z));
    __half l0w = __float2half_rn(v.w - __half2float(h0w));
    ((__half2*)g_A0)[idx * 2]     = __halves2half2(h0x, h0y);
    ((__half2*)g_A0)[idx * 2 + 1] = __halves2half2(h0z, h0w);
    ((__half2*)g_A1)[idx * 2]     = __halves2half2(l0x, l0y);
    ((__half2*)g_A1)[idx * 2 + 1] = __halves2half2(l0z, l0w);
}

// ============================================================
// K-1b: per-row e2 for all 513 codes + fp16 limb split of 512*emb
//       (rows 0..511) into g_B0/g_B1 [n][k]. Warp per row.
// ============================================================
__global__ __launch_bounds__(256) void k_split_b(const float* __restrict__ emb) {
    int gw   = (blockIdx.x * 256 + threadIdx.x) >> 5;
    int lane = threadIdx.x & 31;
    if (gw >= NCODE) return;
    float4 v = ((const float4*)emb)[(size_t)gw * 32 + lane];
    float s = v.x * v.x;
    s = fmaf(v.y, v.y, s);
    s = fmaf(v.z, v.z, s);
    s = fmaf(v.w, v.w, s);
#pragma unroll
    for (int off = 16; off; off >>= 1) s += __shfl_xor_sync(0xffffffffu, s, off);
    if (lane == 0) g_e2[gw] = s;
    if (gw < NE) {
        const float* vp = &v.x;
        __half h[4], l[4];
#pragma unroll
        for (int q = 0; q < 4; q++) {
            float b = vp[q] * 512.0f;              // exact scaling
            h[q] = __float2half_rn(b);
            l[q] = __float2half_rn(b - __half2float(h[q]));
        }
        size_t base = (size_t)gw * 64 + lane * 2;  // half2 index
        ((__half2*)g_B0)[base]     = __halves2half2(h[0], h[1]);
        ((__half2*)g_B0)[base + 1] = __halves2half2(h[2], h[3]);
        ((__half2*)g_B1)[base]     = __halves2half2(l[0], l[1]);
        ((__half2*)g_B1)[base + 1] = __halves2half2(l[2], l[3]);
    }
}

// ============================================================
// K1: fused fp16 m16n8k16 3-product GEMM (BM=64, BN=512, K=128)
//     + epilogue (d assembly, argmin over 513, move bits).
// Smem rows padded to 48 B: cp.async-aligned + conflict-free frags.
// ============================================================
#define E2S_OFF    0
#define AS_OFF     2176        // 2 buf x (hi 3072B + lo 3072B) = 12288
#define ABUF_STR   6144
#define ALO_OFF    3072
#define BS_OFF     14464       // 2 buf x (hi 24576B + lo 24576B) = 98304
#define BBUF_STR   49152
#define BLO_OFF    24576
#define SD_OFF     2176        // epilogue overlay
#define SD_STRIDE  536
#define SMEM_BYTES 139392

__global__ void __launch_bounds__(512, 1)
k_gemm_fused(const float* __restrict__ A, const float* __restrict__ E) {
    extern __shared__ char smem[];
    float* e2s = (float*)(smem + E2S_OFF);
    const uint32_t sb = smem_u32(smem);
    const int tid  = threadIdx.x;
    const int mb   = blockIdx.x;
    const int wid  = tid >> 5;
    const int lane = tid & 31;
    const int wm   = wid & 3;        // m strip (16 rows)
    const int wn   = wid >> 2;       // n strip (128 cols)
    const int g    = lane >> 2;      // group id 0..7
    const int cc   = lane & 3;       // thread in group

    for (int i = tid; i < NCODE; i += 512) e2s[i] = g_e2[i];

    // ---- staging (chunk = 16 k-columns) ----
    auto stage = [&](int c, int buf) {
        const int k0 = c * 16;
        // A: 2 limbs x 64 rows x 2 16B-pieces = 256 cpa16
        if (tid < 256) {
            int m = tid >> 2, lim = (tid >> 1) & 1, q = tid & 1;
            const __half* src = (lim ? g_A1 : g_A0) +
                                (size_t)(mb * 64 + m) * 128 + k0 + q * 8;
            cpa16(sb + AS_OFF + buf * ABUF_STR + lim * ALO_OFF +
                      (uint32_t)(m * 48 + q * 16), src);
        }
        // B: 2 limbs x 512 rows x 2 pieces = 2048 cpa16 -> 4 per thread
#pragma unroll
        for (int i = 0; i < 4; i++) {
            int e = tid + i * 512;
            int lim = e >> 10;
            int r = e & 1023;
            int n = r >> 1, q = r & 1;
            const __half* src = (lim ? g_B1 : g_B0) +
                                (size_t)n * 128 + k0 + q * 8;
            cpa16(sb + BS_OFF + buf * BBUF_STR + lim * BLO_OFF +
                      (uint32_t)(n * 48 + q * 16), src);
        }
        cpa_commit();
    };

    float acc[16][4];
#pragma unroll
    for (int i = 0; i < 16; i++)
#pragma unroll
        for (int j = 0; j < 4; j++) acc[i][j] = 0.0f;

    stage(0, 0);
    for (int c = 0; c < 8; c++) {
        cpa_wait0();
        __syncthreads();
        if (c < 7) stage(c + 1, (c + 1) & 1);

        // halfs, row stride 24 halfs (48 B)
        const __half* A0 = (const __half*)(smem + AS_OFF + (c & 1) * ABUF_STR);
        const __half* A1 = A0 + 1536;   // ALO_OFF bytes
        const __half* B0 = (const __half*)(smem + BS_OFF + (c & 1) * BBUF_STR);
        const __half* B1 = B0 + 12288;  // BLO_OFF bytes

        unsigned ah[4], al[4];
        {
            const int r0 = (wm * 16 + g) * 24;
            const int r8 = (wm * 16 + g + 8) * 24;
            ah[0] = *(const unsigned*)(A0 + r0 + 2 * cc);
            ah[1] = *(const unsigned*)(A0 + r8 + 2 * cc);
            ah[2] = *(const unsigned*)(A0 + r0 + 2 * cc + 8);
            ah[3] = *(const unsigned*)(A0 + r8 + 2 * cc + 8);
            al[0] = *(const unsigned*)(A1 + r0 + 2 * cc);
            al[1] = *(const unsigned*)(A1 + r8 + 2 * cc);
            al[2] = *(const unsigned*)(A1 + r0 + 2 * cc + 8);
            al[3] = *(const unsigned*)(A1 + r8 + 2 * cc + 8);
        }
#pragma unroll
        for (int nb = 0; nb < 16; nb++) {
            const int nrow = (wn * 128 + nb * 8 + g) * 24;
            unsigned bh0 = *(const unsigned*)(B0 + nrow + 2 * cc);
            unsigned bh1 = *(const unsigned*)(B0 + nrow + 2 * cc + 8);
            unsigned bl0 = *(const unsigned*)(B1 + nrow + 2 * cc);
            unsigned bl1 = *(const unsigned*)(B1 + nrow + 2 * cc + 8);
            mma16(acc[nb], ah, bh0, bh1);   // A_hi * B_hi
            mma16(acc[nb], ah, bl0, bl1);   // A_hi * B_lo
            mma16(acc[nb], al, bh0, bh1);   // A_lo * B_hi
        }
        __syncthreads();
    }

    // ---- dump acc fragments to smem d-buffer (overlays tiles) ----
    float* sd = (float*)(smem + SD_OFF);
    {
        const int row0 = wm * 16 + g;
#pragma unroll
        for (int nb = 0; nb < 16; nb++) {
            const int col = wn * 128 + nb * 8 + 2 * cc;
            *(float2*)&sd[(size_t)row0 * SD_STRIDE + col] =
                make_float2(acc[nb][0], acc[nb][1]);
            *(float2*)&sd[(size_t)(row0 + 8) * SD_STRIDE + col] =
                make_float2(acc[nb][2], acc[nb][3]);
        }
    }
    __syncthreads();

    // ---- row scan: 8 threads per row, strided cols ----
    const int t   = tid & 7;
    const int rid = tid >> 3;
    const int row_g = mb * 64 + rid;

    // ks2 + dot with code 512 (fp32 from original inputs)
    float ks2 = 0.0f, dt = 0.0f;
    {
        const float4* kr = (const float4*)A + (size_t)row_g * 32;
        const float4* er = (const float4*)E + (size_t)512 * 32;
#pragma unroll
        for (int j = 0; j < 4; j++) {
            float4 a = kr[t * 4 + j];
            float4 e = __ldg(&er[t * 4 + j]);
            ks2 = fmaf(a.x, a.x, ks2); ks2 = fmaf(a.y, a.y, ks2);
            ks2 = fmaf(a.z, a.z, ks2); ks2 = fmaf(a.w, a.w, ks2);
            dt  = fmaf(a.x, e.x, dt);  dt  = fmaf(a.y, e.y, dt);
            dt  = fmaf(a.z, e.z, dt);  dt  = fmaf(a.w, e.w, dt);
        }
#pragma unroll
        for (int o = 1; o < 8; o <<= 1) {
            ks2 += __shfl_xor_sync(0xffffffffu, ks2, o);
            dt  += __shfl_xor_sync(0xffffffffu, dt, o);
        }
    }
    float d512 = (ks2 + e2s[512]) - 2.0f * dt;

    // dot' = 512*dot  =>  2*dot = dot' * (1/256), exact power-of-2 rescale
    const float RS = 1.0f / 256.0f;
    const float* sdr = sd + (size_t)rid * SD_STRIDE;
    float best = 3.4e38f;
    int   bi = 0;
    float dprev = 0.0f;
    unsigned word = 0;
    const unsigned shift = (unsigned)(tid & 24);  // 8 * (lane group)
#pragma unroll 4
    for (int k = 0; k < 64; k++) {
        float d = (ks2 + e2s[8 * k + t]) - RS * sdr[8 * k + t];
        if (k > 0) {
            float dnb = __shfl_down_sync(0xffffffffu, dprev, 1, 8);
            float d0  = __shfl_sync(0xffffffffu, d, 0, 8);
            float nxt = (t == 7) ? d0 : dnb;
            unsigned Bb = __ballot_sync(0xffffffffu, dprev > nxt);
            word |= ((Bb >> shift) & 0xFFu) << (((k - 1) & 3) * 8);
            if (((k - 1) & 3) == 3) {
                if (t == 0) g_move[(size_t)row_g * 16 + ((k - 1) >> 2)] = word;
                word = 0;
            }
        }
        if (d < best) { best = d; bi = 8 * k + t; }
        dprev = d;
    }
    {
        float dnb = __shfl_down_sync(0xffffffffu, dprev, 1, 8);
        unsigned Bb = __ballot_sync(0xffffffffu, (t < 7) && (dprev > dnb));
        word |= ((Bb >> shift) & 0xFFu) << 24;
        if (t == 0) g_move[(size_t)row_g * 16 + 15] = word;
    }
#pragma unroll
    for (int o = 1; o < 8; o <<= 1) {
        float ov = __shfl_xor_sync(0xffffffffu, best, o);
        int   oi = __shfl_xor_sync(0xffffffffu, bi, o);
        if (ov < best || (ov == best && oi < bi)) { best = ov; bi = oi; }
    }
    if (d512 < best) bi = 512;
    if (t == 0) g_minidx[row_g] = bi;
}

// ============================================================
// K3a: chunk transition tables
// ============================================================
__global__ __launch_bounds__(512) void k_scantbl(void) {
    const int c   = blockIdx.x;     // 0..14
    const int b   = blockIdx.y;
    const int tid = threadIdx.x;
    __shared__ unsigned mw[64][16];
    const int t0 = c * 64 + 1;
#pragma unroll
    for (int r = 0; r < 2; r++) {
        int i = tid + r * 512;
        mw[i >> 4][i & 15] =
            g_move[(size_t)(b * 1024 + t0 + (i >> 4)) * 16 + (i & 15)];
    }
    __syncthreads();
    int ind = tid;
    for (int s = 0; s < 64; s++) ind += (mw[s][ind >> 5] >> (ind & 31)) & 1;
    g_tbl[((size_t)b * 15 + c) * 512 + tid] = (unsigned short)ind;
}

// ============================================================
// K3c: compute chunk entry state in-block, re-simulate, emit enc
// ============================================================
__global__ __launch_bounds__(64) void k_emit_enc(const unsigned char* __restrict__ mask) {
    const int c   = blockIdx.x;     // 0..15
    const int b   = blockIdx.y;
    const int tid = threadIdx.x;
    __shared__ unsigned mw[63][16];
    __shared__ int s_ent;
    const int t0 = c * 64 + 1;
    for (int i = tid; i < 63 * 16; i += 64)
        mw[i >> 4][i & 15] =
            g_move[(size_t)(b * 1024 + t0 + (i >> 4)) * 16 + (i & 15)];
    if (tid == 0) {
        int ind = g_minidx[b * 1024];
        if (ind > 511) ind = 511;
        if (mask[b]) ind = 0;
        for (int cc = 0; cc < c; cc++)
            ind = g_tbl[((size_t)b * 15 + cc) * 512 + ind];
        s_ent = ind;
    }
    __syncthreads();
    int ind = s_ent;
    for (int s = 0; s < tid; s++) ind += (mw[s][ind >> 5] >> (ind & 31)) & 1;
    g_enc[b * 1024 + c * 64 + tid] = ind;
}

// ============================================================
// K4: fused gathers + losses + key_hard + energy. Warp per (b,t).
// ============================================================
__global__ __launch_bounds__(256) void k_final(const float* __restrict__ ks,
                                               const float* __restrict__ emb,
                                               float* __restrict__ out) {
    const int row  = blockIdx.x * 8 + (threadIdx.x >> 5);
    const int lane = threadIdx.x & 31;
    const float4* k4 = (const float4*)ks + (size_t)row * 32;
    const float4* e4 = (const float4*)emb;

    int here = g_enc[row];
    int nxt  = here + 1; if (nxt > 511) nxt = 511;
    int mi   = g_minidx[row];

    float4 a  = k4[lane];
    float4 eh = e4[(size_t)here * 32 + lane];
    float4 en = e4[(size_t)nxt * 32 + lane];
    float4 em = e4[(size_t)mi * 32 + lane];

    float sh, sn, sm;
    {
        float d0 = a.x - eh.x, d1 = a.y - eh.y, d2 = a.z - eh.z, d3 = a.w - eh.w;
        sh = d0 * d0; sh = fmaf(d1, d1, sh); sh = fmaf(d2, d2, sh); sh = fmaf(d3, d3, sh);
    }
    {
        float d0 = a.x - en.x, d1 = a.y - en.y, d2 = a.z - en.z, d3 = a.w - en.w;
        sn = d0 * d0; sn = fmaf(d1, d1, sn); sn = fmaf(d2, d2, sn); sn = fmaf(d3, d3, sn);
    }
    {
        float d0 = a.x - em.x, d1 = a.y - em.y, d2 = a.z - em.z, d3 = a.w - em.w;
        sm = d0 * d0; sm = fmaf(d1, d1, sm); sm = fmaf(d2, d2, sm); sm = fmaf(d3, d3, sm);
    }
#pragma unroll
    for (int off = 16; off; off >>= 1) {
        sh += __shfl_xor_sync(0xffffffffu, sh, off);
        sn += __shfl_xor_sync(0xffffffffu, sn, off);
        sm += __shfl_xor_sync(0xffffffffu, sm, off);
    }

    float4 o;
    o.x = a.x + (eh.x - a.x);
    o.y = a.y + (eh.y - a.y);
    o.z = a.z + (eh.z - a.z);
    o.w = a.w + (eh.w - a.w);
    ((float4*)(out + OFF_KH))[(size_t)row * 32 + lane] = o;

    if (lane == 0) {
        float Lh = sh + sh * 0.2f;
        float Ln = sn + sn * 0.2f;
        float Lm = sm + sm * 0.2f;
        float dif = sn - sh;
        float energy = dif + dif * 0.2f;
        float lmh = (Lm < Lh) ? Lm : 0.0f;
        float lmn = (Lm < Ln) ? Lm : 0.0f;
        out[OFF_LH  + row] = (Lh - Ln) - lmh;
        out[OFF_LNX + row] = (Ln - Lh) - lmn;
        out[OFF_ENC + row] = (float)here;
        g_energy[row] = energy;
    }
}

// ============================================================
// K5: per-batch reductions
// ============================================================
__global__ __launch_bounds__(256) void k_reduce_b(void) {
    const int b   = blockIdx.x;
    const int tid = threadIdx.x;
    __shared__ float sE[256], sL[256];
    __shared__ int   sMn[256], sMx[256];
    const float* eb = g_energy + b * 1024;
    const int*   cb = g_enc + b * 1024;

    float aE = 0.0f, aL = 0.0f;
    int mn = 1 << 30, mx = -1;
    for (int t = tid; t < 1024; t += 256) {
        aE += eb[t];
        int cv = cb[t];
        mn = min(mn, cv);
        mx = max(mx, cv);
    }
    const float EPS = (float)(1e-6 / 512.0);
    for (int t = tid + 1; t < 1024; t += 256) {
        float ch = (cb[t] != cb[t - 1]) ? 0.0f : (eb[t] - eb[t - 1]);
        aL += fmaxf(ch + EPS, 0.0f);
    }
    sE[tid] = aE; sL[tid] = aL; sMn[tid] = mn; sMx[tid] = mx;
    __syncthreads();
    for (int s = 128; s; s >>= 1) {
        if (tid < s) {
            sE[tid] += sE[tid + s];
            sL[tid] += sL[tid + s];
            sMn[tid] = min(sMn[tid], sMn[tid + s]);
            sMx[tid] = max(sMx[tid], sMx[tid + s]);
        }
        __syncthreads();
    }
    if (tid == 0) {
        g_pE[b]  = sE[0];
        g_pL[b]  = sL[0];
        g_rng[b] = sMx[0] - sMn[0];
    }
}

// ============================================================
// K6: final scalars
// ============================================================
__global__ void k_scalars(float* __restrict__ out) {
    int tid = threadIdx.x;  // 64
    __shared__ float sE[64], sL[64];
    __shared__ int   sR[64];
    sE[tid] = g_pE[tid]; sL[tid] = g_pL[tid]; sR[tid] = g_rng[tid];
    __syncthreads();
    for (int s = 32; s; s >>= 1) {
        if (tid < s) {
            sE[tid] += sE[tid + s];
            sL[tid] += sL[tid + s];
            sR[tid] = max(sR[tid], sR[tid + s]);
        }
        __syncthreads();
    }
    if (tid == 0) {
        out[OFF_EM]  = sE[0] / 65536.0f;
        out[OFF_LED] = sL[0] / 65472.0f;
        out[OFF_V]   = (float)sR[0];
    }
}

// ============================================================
extern "C" void kernel_launch(void* const* d_in, const int* in_sizes, int n_in,
                              void* d_out, int out_size) {
    const float* ks = nullptr;
    const float* emb = nullptr;
    const unsigned char* mask = nullptr;
    for (int i = 0; i < n_in; i++) {
        if (in_sizes[i] == ROWS * D_)        ks   = (const float*)d_in[i];
        else if (in_sizes[i] == NCODE * D_)  emb  = (const float*)d_in[i];
        else if (in_sizes[i] == B_)          mask = (const unsigned char*)d_in[i];
    }
    float* out = (float*)d_out;

    cudaFuncSetAttribute(k_gemm_fused,
                         cudaFuncAttributeMaxDynamicSharedMemorySize, SMEM_BYTES);

    k_split_a<<<ROWS * D_ / 4 / 256, 256>>>(ks);
    k_split_b<<<(NCODE * 32 + 255) / 256, 256>>>(emb);
    k_gemm_fused<<<ROWS / 64, 512, SMEM_BYTES>>>(ks, emb);
    k_scantbl<<<dim3(15, B_), 512>>>();
    k_emit_enc<<<dim3(16, B_), 64>>>(mask);
    k_final<<<ROWS / 8, 256>>>(ks, emb, out);
    k_reduce_b<<<B_, 256>>>();
    k_scalars<<<1, 64>>>(out);
}

// round 12
// speedup vs baseline: 2.3785x; 1.0024x over previous
#include <cuda_runtime.h>
#include <cuda_fp16.h>
#include <cstdint>

typedef unsigned long long ull;

#define B_    64
#define T_    1024
#define D_    128
#define NE    512
#define NCODE 513
#define ROWS  (B_ * T_)   // 65536

// ---- output layout (float32, tuple order) ----
#define OFF_KH  0
#define OFF_ENC 8388608
#define OFF_V   8454144
#define OFF_LH  8454145
#define OFF_LNX 8519681
#define OFF_EM  8585217
#define OFF_LED 8585218

// ---- scratch ----
__device__ __half         g_B0[(size_t)NE * D_];     // fp16 hi limb of 512*emb [n][k]
__device__ __half         g_B1[(size_t)NE * D_];     // fp16 lo limb
__device__ float          g_e2[NCODE];
__device__ int            g_minidx[ROWS];
__device__ unsigned       g_move[(size_t)ROWS * 16];
__device__ unsigned short g_tbl[(size_t)B_ * 15 * 512];
__device__ int            g_enc[ROWS];
__device__ float          g_energy[ROWS];
__device__ float          g_pE[B_], g_pL[B_];
__device__ int            g_rng[B_];

// ============================================================
// helpers
// ============================================================
__device__ __forceinline__ uint32_t smem_u32(const void* p) {
    uint32_t a;
    asm("{ .reg .u64 t; cvta.to.shared.u64 t, %1; cvt.u32.u64 %0, t; }"
        : "=r"(a) : "l"(p));
    return a;
}
__device__ __forceinline__ void cpa16(uint32_t dst, const void* src) {
    asm volatile("cp.async.ca.shared.global [%0], [%1], 16;"
                 :: "r"(dst), "l"(src));
}
__device__ __forceinline__ void cpa_commit(void) {
    asm volatile("cp.async.commit_group;");
}
__device__ __forceinline__ void cpa_wait0(void) {
    asm volatile("cp.async.wait_group 0;");
}
__device__ __forceinline__ void cpa_wait1(void) {
    asm volatile("cp.async.wait_group 1;");
}
__device__ __forceinline__ void mma16(float* d, const unsigned* a,
                                      unsigned b0, unsigned b1) {
    asm("mma.sync.aligned.m16n8k16.row.col.f32.f16.f16.f32 "
        "{%0,%1,%2,%3}, {%4,%5,%6,%7}, {%8,%9}, {%0,%1,%2,%3};"
        : "+f"(d[0]), "+f"(d[1]), "+f"(d[2]), "+f"(d[3])
        : "r"(a[0]), "r"(a[1]), "r"(a[2]), "r"(a[3]), "r"(b0), "r"(b1));
}

// ============================================================
// K-1b: per-row e2 for all 513 codes + fp16 limb split of 512*emb
//       (rows 0..511) into g_B0/g_B1 [n][k]. Warp per row.
// ============================================================
__global__ __launch_bounds__(256) void k_split_b(const float* __restrict__ emb) {
    int gw   = (blockIdx.x * 256 + threadIdx.x) >> 5;
    int lane = threadIdx.x & 31;
    if (gw >= NCODE) return;
    float4 v = ((const float4*)emb)[(size_t)gw * 32 + lane];
    float s = v.x * v.x;
    s = fmaf(v.y, v.y, s);
    s = fmaf(v.z, v.z, s);
    s = fmaf(v.w, v.w, s);
#pragma unroll
    for (int off = 16; off; off >>= 1) s += __shfl_xor_sync(0xffffffffu, s, off);
    if (lane == 0) g_e2[gw] = s;
    if (gw < NE) {
        const float* vp = &v.x;
        __half h[4], l[4];
#pragma unroll
        for (int q = 0; q < 4; q++) {
            float b = vp[q] * 512.0f;              // exact scaling
            h[q] = __float2half_rn(b);
            l[q] = __float2half_rn(b - __half2float(h[q]));
        }
        size_t base = (size_t)gw * 64 + lane * 2;  // half2 index
        ((__half2*)g_B0)[base]     = __halves2half2(h[0], h[1]);
        ((__half2*)g_B0)[base + 1] = __halves2half2(h[2], h[3]);
        ((__half2*)g_B1)[base]     = __halves2half2(l[0], l[1]);
        ((__half2*)g_B1)[base + 1] = __halves2half2(l[2], l[3]);
    }
}

// ============================================================
// K1: fused fp16 m16n8k16 3-product GEMM (BM=64, BN=512, K=128)
//     with IN-KERNEL A limb conversion + epilogue (d assembly,
//     argmin over 513, move bits).
// A limbs: 8 resident k16-chunks, 48B rows. B: double-buffered.
// ============================================================
#define E2S_OFF    0
#define AL_OFF     2176        // 8 chunks x (hi 3072B + lo 3072B) = 49152
#define ACH_STR    6144
#define ALO_OFF    3072
#define BS_OFF     51328       // 2 buf x (hi 24576B + lo 24576B) = 98304
#define BBUF_STR   49152
#define BLO_OFF    24576
#define AF32_OFF   149632      // transient 64x128 fp32 tile = 32768
#define SD_OFF     2176        // epilogue overlay (A/B tiles dead)
#define SD_STRIDE  536
#define SMEM_BYTES 182400

__global__ void __launch_bounds__(512, 1)
k_gemm_fused(const float* __restrict__ A, const float* __restrict__ E) {
    extern __shared__ char smem[];
    float* e2s = (float*)(smem + E2S_OFF);
    const uint32_t sb = smem_u32(smem);
    const int tid  = threadIdx.x;
    const int mb   = blockIdx.x;
    const int wid  = tid >> 5;
    const int lane = tid & 31;
    const int wm   = wid & 3;        // m strip (16 rows)
    const int wn   = wid >> 2;       // n strip (128 cols)
    const int g    = lane >> 2;      // group id 0..7
    const int cc   = lane & 3;       // thread in group

    // ---- B staging (chunk = 16 k-columns) ----
    auto stageB = [&](int c, int buf) {
        const int k0 = c * 16;
#pragma unroll
        for (int i = 0; i < 4; i++) {
            int e = tid + i * 512;
            int lim = e >> 10;
            int r = e & 1023;
            int n = r >> 1, q = r & 1;
            const __half* src = (lim ? g_B1 : g_B0) +
                                (size_t)n * 128 + k0 + q * 8;
            cpa16(sb + BS_OFF + buf * BBUF_STR + lim * BLO_OFF +
                      (uint32_t)(n * 48 + q * 16), src);
        }
        cpa_commit();
    };

    // ---- group 0: A fp32 tile (32KB, contiguous rows) ----
    {
        const float* Abase = A + (size_t)mb * 64 * 128;
#pragma unroll
        for (int i = 0; i < 4; i++) {
            int e = tid + i * 512;      // 16B piece index, 0..2047
            cpa16(sb + AF32_OFF + (uint32_t)e * 16, Abase + e * 4);
        }
        cpa_commit();
    }
    // ---- group 1: B chunk 0 ----
    stageB(0, 0);

    for (int i = tid; i < NCODE; i += 512) e2s[i] = g_e2[i];

    // ---- wait for A (B0 may still be in flight), convert to limbs ----
    cpa_wait1();
    __syncthreads();
    {
        const float2* Af = (const float2*)(smem + AF32_OFF);
#pragma unroll
        for (int it = 0; it < 8; it++) {
            int e = tid + it * 512;     // half2-pair index, 0..4095
            int m = e >> 6, j = e & 63; // row, k-pair (k = 2j)
            float2 v = Af[m * 64 + j];
            __half hx = __float2half_rn(v.x), hy = __float2half_rn(v.y);
            __half lx = __float2half_rn(v.x - __half2float(hx));
            __half ly = __float2half_rn(v.y - __half2float(hy));
            uint32_t off = (uint32_t)(AL_OFF + (j >> 3) * ACH_STR +
                                      m * 48 + (j & 7) * 4);
            *(__half2*)(smem + off)           = __halves2half2(hx, hy);
            *(__half2*)(smem + off + ALO_OFF) = __halves2half2(lx, ly);
        }
    }

    float acc[16][4];
#pragma unroll
    for (int i = 0; i < 16; i++)
#pragma unroll
        for (int j = 0; j < 4; j++) acc[i][j] = 0.0f;

    for (int c = 0; c < 8; c++) {
        cpa_wait0();
        __syncthreads();
        if (c < 7) stageB(c + 1, (c + 1) & 1);

        // A limbs resident per chunk; halfs, row stride 24 halfs (48B)
        const __half* A0 = (const __half*)(smem + AL_OFF + c * ACH_STR);
        const __half* A1 = A0 + 1536;   // ALO_OFF bytes
        const __half* B0 = (const __half*)(smem + BS_OFF + (c & 1) * BBUF_STR);
        const __half* B1 = B0 + 12288;  // BLO_OFF bytes

        unsigned ah[4], al[4];
        {
            const int r0 = (wm * 16 + g) * 24;
            const int r8 = (wm * 16 + g + 8) * 24;
            ah[0] = *(const unsigned*)(A0 + r0 + 2 * cc);
            ah[1] = *(const unsigned*)(A0 + r8 + 2 * cc);
            ah[2] = *(const unsigned*)(A0 + r0 + 2 * cc + 8);
            ah[3] = *(const unsigned*)(A0 + r8 + 2 * cc + 8);
            al[0] = *(const unsigned*)(A1 + r0 + 2 * cc);
            al[1] = *(const unsigned*)(A1 + r8 + 2 * cc);
            al[2] = *(const unsigned*)(A1 + r0 + 2 * cc + 8);
            al[3] = *(const unsigned*)(A1 + r8 + 2 * cc + 8);
        }
#pragma unroll
        for (int nb = 0; nb < 16; nb++) {
            const int nrow = (wn * 128 + nb * 8 + g) * 24;
            unsigned bh0 = *(const unsigned*)(B0 + nrow + 2 * cc);
            unsigned bh1 = *(const unsigned*)(B0 + nrow + 2 * cc + 8);
            unsigned bl0 = *(const unsigned*)(B1 + nrow + 2 * cc);
            unsigned bl1 = *(const unsigned*)(B1 + nrow + 2 * cc + 8);
            mma16(acc[nb], ah, bh0, bh1);   // A_hi * B_hi
            mma16(acc[nb], ah, bl0, bl1);   // A_hi * B_lo
            mma16(acc[nb], al, bh0, bh1);   // A_lo * B_hi
        }
        __syncthreads();
    }

    // ---- dump acc fragments to smem d-buffer (overlays tiles) ----
    float* sd = (float*)(smem + SD_OFF);
    {
        const int row0 = wm * 16 + g;
#pragma unroll
        for (int nb = 0; nb < 16; nb++) {
            const int col = wn * 128 + nb * 8 + 2 * cc;
            *(float2*)&sd[(size_t)row0 * SD_STRIDE + col] =
                make_float2(acc[nb][0], acc[nb][1]);
            *(float2*)&sd[(size_t)(row0 + 8) * SD_STRIDE + col] =
                make_float2(acc[nb][2], acc[nb][3]);
        }
    }
    __syncthreads();

    // ---- row scan: 8 threads per row, strided cols ----
    const int t   = tid & 7;
    const int rid = tid >> 3;
    const int row_g = mb * 64 + rid;

    // ks2 + dot with code 512 (fp32 from original inputs)
    float ks2 = 0.0f, dt = 0.0f;
    {
        const float4* kr = (const float4*)A + (size_t)row_g * 32;
        const float4* er = (const float4*)E + (size_t)512 * 32;
#pragma unroll
        for (int j = 0; j < 4; j++) {
            float4 a = kr[t * 4 + j];
            float4 e = __ldg(&er[t * 4 + j]);
            ks2 = fmaf(a.x, a.x, ks2); ks2 = fmaf(a.y, a.y, ks2);
            ks2 = fmaf(a.z, a.z, ks2); ks2 = fmaf(a.w, a.w, ks2);
            dt  = fmaf(a.x, e.x, dt);  dt  = fmaf(a.y, e.y, dt);
            dt  = fmaf(a.z, e.z, dt);  dt  = fmaf(a.w, e.w, dt);
        }
#pragma unroll
        for (int o = 1; o < 8; o <<= 1) {
            ks2 += __shfl_xor_sync(0xffffffffu, ks2, o);
            dt  += __shfl_xor_sync(0xffffffffu, dt, o);
        }
    }
    float d512 = (ks2 + e2s[512]) - 2.0f * dt;

    // dot' = 512*dot  =>  2*dot = dot' * (1/256), exact power-of-2 rescale
    const float RS = 1.0f / 256.0f;
    const float* sdr = sd + (size_t)rid * SD_STRIDE;
    float best = 3.4e38f;
    int   bi = 0;
    float dprev = 0.0f;
    unsigned word = 0;
    const unsigned shift = (unsigned)(tid & 24);  // 8 * (lane group)
#pragma unroll 4
    for (int k = 0; k < 64; k++) {
        float d = (ks2 + e2s[8 * k + t]) - RS * sdr[8 * k + t];
        if (k > 0) {
            float dnb = __shfl_down_sync(0xffffffffu, dprev, 1, 8);
            float d0  = __shfl_sync(0xffffffffu, d, 0, 8);
            float nxt = (t == 7) ? d0 : dnb;
            unsigned Bb = __ballot_sync(0xffffffffu, dprev > nxt);
            word |= ((Bb >> shift) & 0xFFu) << (((k - 1) & 3) * 8);
            if (((k - 1) & 3) == 3) {
                if (t == 0) g_move[(size_t)row_g * 16 + ((k - 1) >> 2)] = word;
                word = 0;
            }
        }
        if (d < best) { best = d; bi = 8 * k + t; }
        dprev = d;
    }
    {
        float dnb = __shfl_down_sync(0xffffffffu, dprev, 1, 8);
        unsigned Bb = __ballot_sync(0xffffffffu, (t < 7) && (dprev > dnb));
        word |= ((Bb >> shift) & 0xFFu) << 24;
        if (t == 0) g_move[(size_t)row_g * 16 + 15] = word;
    }
#pragma unroll
    for (int o = 1; o < 8; o <<= 1) {
        float ov = __shfl_xor_sync(0xffffffffu, best, o);
        int   oi = __shfl_xor_sync(0xffffffffu, bi, o);
        if (ov < best || (ov == best && oi < bi)) { best = ov; bi = oi; }
    }
    if (d512 < best) bi = 512;
    if (t == 0) g_minidx[row_g] = bi;
}

// ============================================================
// K3a: chunk transition tables (fully unrolled dependent chain)
// ============================================================
__global__ __launch_bounds__(512) void k_scantbl(void) {
    const int c   = blockIdx.x;     // 0..14
    const int b   = blockIdx.y;
    const int tid = threadIdx.x;
    __shared__ unsigned mw[64][16];
    const int t0 = c * 64 + 1;
#pragma unroll
    for (int r = 0; r < 2; r++) {
        int i = tid + r * 512;
        mw[i >> 4][i & 15] =
            g_move[(size_t)(b * 1024 + t0 + (i >> 4)) * 16 + (i & 15)];
    }
    __syncthreads();
    int ind = tid;
#pragma unroll
    for (int s = 0; s < 64; s++) ind += (mw[s][ind >> 5] >> (ind & 31)) & 1;
    g_tbl[((size_t)b * 15 + c) * 512 + tid] = (unsigned short)ind;
}

// ============================================================
// K3c: emit enc. grid (2, 64) x 512 threads. Each block owns 8
// chunks (512 positions); thread 0 walks the table composition
// once and stores all 8 entry states; chunks re-simulate in parallel.
// ============================================================
__global__ __launch_bounds__(512) void k_emit_enc(const unsigned char* __restrict__ mask) {
    const int half = blockIdx.x;    // 0/1 -> chunks 0..7 / 8..15
    const int b    = blockIdx.y;
    const int tid  = threadIdx.x;
    __shared__ unsigned mw[511][16];
    __shared__ int s_ent[8];
    const int tbase = half * 512 + 1;
    for (int i = tid; i < 511 * 16; i += 512)
        mw[i >> 4][i & 15] =
            g_move[(size_t)(b * 1024 + tbase + (i >> 4)) * 16 + (i & 15)];
    if (tid == 0) {
        int ind = g_minidx[b * 1024];
        if (ind > 511) ind = 511;
        if (mask[b]) ind = 0;
        for (int cg = 0; cg < half * 8; cg++)
            ind = g_tbl[((size_t)b * 15 + cg) * 512 + ind];
        s_ent[0] = ind;
        for (int q = 1; q < 8; q++) {
            int cg = half * 8 + q - 1;
            ind = g_tbl[((size_t)b * 15 + cg) * 512 + ind];
            s_ent[q] = ind;
        }
    }
    __syncthreads();
    const int cl = tid >> 6;        // chunk-local 0..7
    const int s  = tid & 63;        // position in chunk
    int ind = s_ent[cl];
    for (int ss = 0; ss < s; ss++) {
        int r = cl * 64 + ss;       // local move row (t = tbase + r)
        ind += (mw[r][ind >> 5] >> (ind & 31)) & 1;
    }
    g_enc[b * 1024 + (half * 8 + cl) * 64 + s] = ind;
}

// ============================================================
// K4: fused gathers + losses + key_hard + energy. Warp per (b,t).
// ============================================================
__global__ __launch_bounds__(256) void k_final(const float* __restrict__ ks,
                                               const float* __restrict__ emb,
                                               float* __restrict__ out) {
    const int row  = blockIdx.x * 8 + (threadIdx.x >> 5);
    const int lane = threadIdx.x & 31;
    const float4* k4 = (const float4*)ks + (size_t)row * 32;
    const float4* e4 = (const float4*)emb;

    int here = g_enc[row];
    int nxt  = here + 1; if (nxt > 511) nxt = 511;
    int mi   = g_minidx[row];

    float4 a  = k4[lane];
    float4 eh = e4[(size_t)here * 32 + lane];
    float4 en = e4[(size_t)nxt * 32 + lane];
    float4 em = e4[(size_t)mi * 32 + lane];

    float sh, sn, sm;
    {
        float d0 = a.x - eh.x, d1 = a.y - eh.y, d2 = a.z - eh.z, d3 = a.w - eh.w;
        sh = d0 * d0; sh = fmaf(d1, d1, sh); sh = fmaf(d2, d2, sh); sh = fmaf(d3, d3, sh);
    }
    {
        float d0 = a.x - en.x, d1 = a.y - en.y, d2 = a.z - en.z, d3 = a.w - en.w;
        sn = d0 * d0; sn = fmaf(d1, d1, sn); sn = fmaf(d2, d2, sn); sn = fmaf(d3, d3, sn);
    }
    {
        float d0 = a.x - em.x, d1 = a.y - em.y, d2 = a.z - em.z, d3 = a.w - em.w;
        sm = d0 * d0; sm = fmaf(d1, d1, sm); sm = fmaf(d2, d2, sm); sm = fmaf(d3, d3, sm);
    }
#pragma unroll
    for (int off = 16; off; off >>= 1) {
        sh += __shfl_xor_sync(0xffffffffu, sh, off);
        sn += __shfl_xor_sync(0xffffffffu, sn, off);
        sm += __shfl_xor_sync(0xffffffffu, sm, off);
    }

    float4 o;
    o.x = a.x + (eh.x - a.x);
    o.y = a.y + (eh.y - a.y);
    o.z = a.z + (eh.z - a.z);
    o.w = a.w + (eh.w - a.w);
    ((float4*)(out + OFF_KH))[(size_t)row * 32 + lane] = o;

    if (lane == 0) {
        float Lh = sh + sh * 0.2f;
        float Ln = sn + sn * 0.2f;
        float Lm = sm + sm * 0.2f;
        float dif = sn - sh;
        float energy = dif + dif * 0.2f;
        float lmh = (Lm < Lh) ? Lm : 0.0f;
        float lmn = (Lm < Ln) ? Lm : 0.0f;
        out[OFF_LH  + row] = (Lh - Ln) - lmh;
        out[OFF_LNX + row] = (Ln - Lh) - lmn;
        out[OFF_ENC + row] = (float)here;
        g_energy[row] = energy;
    }
}

// ============================================================
// K5: per-batch reductions
// ============================================================
__global__ __launch_bounds__(256) void k_reduce_b(void) {
    const int b   = blockIdx.x;
    const int tid = threadIdx.x;
    __shared__ float sE[256], sL[256];
    __shared__ int   sMn[256], sMx[256];
    const float* eb = g_energy + b * 1024;
    const int*   cb = g_enc + b * 1024;

    float aE = 0.0f, aL = 0.0f;
    int mn = 1 << 30, mx = -1;
    for (int t = tid; t < 1024; t += 256) {
        aE += eb[t];
        int cv = cb[t];
        mn = min(mn, cv);
        mx = max(mx, cv);
    }
    const float EPS = (float)(1e-6 / 512.0);
    for (int t = tid + 1; t < 1024; t += 256) {
        float ch = (cb[t] != cb[t - 1]) ? 0.0f : (eb[t] - eb[t - 1]);
        aL += fmaxf(ch + EPS, 0.0f);
    }
    sE[tid] = aE; sL[tid] = aL; sMn[tid] = mn; sMx[tid] = mx;
    __syncthreads();
    for (int s = 128; s; s >>= 1) {
        if (tid < s) {
            sE[tid] += sE[tid + s];
            sL[tid] += sL[tid + s];
            sMn[tid] = min(sMn[tid], sMn[tid + s]);
            sMx[tid] = max(sMx[tid], sMx[tid + s]);
        }
        __syncthreads();
    }
    if (tid == 0) {
        g_pE[b]  = sE[0];
        g_pL[b]  = sL[0];
        g_rng[b] = sMx[0] - sMn[0];
    }
}

// ============================================================
// K6: final scalars
// ============================================================
__global__ void k_scalars(float* __restrict__ out) {
    int tid = threadIdx.x;  // 64
    __shared__ float sE[64], sL[64];
    __shared__ int   sR[64];
    sE[tid] = g_pE[tid]; sL[tid] = g_pL[tid]; sR[tid] = g_rng[tid];
    __syncthreads();
    for (int s = 32; s; s >>= 1) {
        if (tid < s) {
            sE[tid] += sE[tid + s];
            sL[tid] += sL[tid + s];
            sR[tid] = max(sR[tid], sR[tid + s]);
        }
        __syncthreads();
    }
    if (tid == 0) {
        out[OFF_EM]  = sE[0] / 65536.0f;
        out[OFF_LED] = sL[0] / 65472.0f;
        out[OFF_V]   = (float)sR[0];
    }
}

// ============================================================
extern "C" void kernel_launch(void* const* d_in, const int* in_sizes, int n_in,
                              void* d_out, int out_size) {
    const float* ks = nullptr;
    const float* emb = nullptr;
    const unsigned char* mask = nullptr;
    for (int i = 0; i < n_in; i++) {
        if (in_sizes[i] == ROWS * D_)        ks   = (const float*)d_in[i];
        else if (in_sizes[i] == NCODE * D_)  emb  = (const float*)d_in[i];
        else if (in_sizes[i] == B_)          mask = (const unsigned char*)d_in[i];
    }
    float* out = (float*)d_out;

    cudaFuncSetAttribute(k_gemm_fused,
                         cudaFuncAttributeMaxDynamicSharedMemorySize, SMEM_BYTES);

    k_split_b<<<(NCODE * 32 + 255) / 256, 256>>>(emb);
    k_gemm_fused<<<ROWS / 64, 512, SMEM_BYTES>>>(ks, emb);
    k_scantbl<<<dim3(15, B_), 512>>>();
    k_emit_enc<<<dim3(2, B_), 512>>>(mask);
    k_final<<<ROWS / 8, 256>>>(ks, emb, out);
    k_reduce_b<<<B_, 256>>>();
    k_scalars<<<1, 64>>>(out);
}

// round 13
// speedup vs baseline: 2.3789x; 1.0002x over previous
#include <cuda_runtime.h>
#include <cuda_fp16.h>
#include <cstdint>

typedef unsigned long long ull;

#define B_    64
#define T_    1024
#define D_    128
#define NE    512
#define NCODE 513
#define ROWS  (B_ * T_)   // 65536

// ---- output layout (float32, tuple order) ----
#define OFF_KH  0
#define OFF_ENC 8388608
#define OFF_V   8454144
#define OFF_LH  8454145
#define OFF_LNX 8519681
#define OFF_EM  8585217
#define OFF_LED 8585218

// ---- scratch ----
__device__ __half         g_B0[(size_t)NE * D_];     // fp16 hi limb of 512*emb [n][k]
__device__ __half         g_B1[(size_t)NE * D_];     // fp16 lo limb
__device__ float          g_e2[NCODE];
__device__ int            g_minidx[ROWS];
__device__ unsigned       g_move[(size_t)ROWS * 16];
__device__ unsigned short g_tbl[(size_t)B_ * 15 * 512];
__device__ int            g_enc[ROWS];
__device__ float          g_energy[ROWS];
__device__ float          g_pE[B_], g_pL[B_];
__device__ int            g_rng[B_];

// ============================================================
// helpers
// ============================================================
__device__ __forceinline__ uint32_t smem_u32(const void* p) {
    uint32_t a;
    asm("{ .reg .u64 t; cvta.to.shared.u64 t, %1; cvt.u32.u64 %0, t; }"
        : "=r"(a) : "l"(p));
    return a;
}
__device__ __forceinline__ void cpa16(uint32_t dst, const void* src) {
    asm volatile("cp.async.ca.shared.global [%0], [%1], 16;"
                 :: "r"(dst), "l"(src));
}
__device__ __forceinline__ void cpa_commit(void) {
    asm volatile("cp.async.commit_group;");
}
__device__ __forceinline__ void cpa_wait0(void) {
    asm volatile("cp.async.wait_group 0;");
}
__device__ __forceinline__ void cpa_wait1(void) {
    asm volatile("cp.async.wait_group 1;");
}
__device__ __forceinline__ void mma16(float* d, const unsigned* a,
                                      unsigned b0, unsigned b1) {
    asm("mma.sync.aligned.m16n8k16.row.col.f32.f16.f16.f32 "
        "{%0,%1,%2,%3}, {%4,%5,%6,%7}, {%8,%9}, {%0,%1,%2,%3};"
        : "+f"(d[0]), "+f"(d[1]), "+f"(d[2]), "+f"(d[3])
        : "r"(a[0]), "r"(a[1]), "r"(a[2]), "r"(a[3]), "r"(b0), "r"(b1));
}

// ============================================================
// K-1b: per-row e2 for all 513 codes + fp16 limb split of 512*emb
//       (rows 0..511) into g_B0/g_B1 [n][k]. Warp per row.
// ============================================================
__global__ __launch_bounds__(256) void k_split_b(const float* __restrict__ emb) {
    int gw   = (blockIdx.x * 256 + threadIdx.x) >> 5;
    int lane = threadIdx.x & 31;
    if (gw >= NCODE) return;
    float4 v = ((const float4*)emb)[(size_t)gw * 32 + lane];
    float s = v.x * v.x;
    s = fmaf(v.y, v.y, s);
    s = fmaf(v.z, v.z, s);
    s = fmaf(v.w, v.w, s);
#pragma unroll
    for (int off = 16; off; off >>= 1) s += __shfl_xor_sync(0xffffffffu, s, off);
    if (lane == 0) g_e2[gw] = s;
    if (gw < NE) {
        const float* vp = &v.x;
        __half h[4], l[4];
#pragma unroll
        for (int q = 0; q < 4; q++) {
            float b = vp[q] * 512.0f;              // exact scaling
            h[q] = __float2half_rn(b);
            l[q] = __float2half_rn(b - __half2float(h[q]));
        }
        size_t base = (size_t)gw * 64 + lane * 2;  // half2 index
        ((__half2*)g_B0)[base]     = __halves2half2(h[0], h[1]);
        ((__half2*)g_B0)[base + 1] = __halves2half2(h[2], h[3]);
        ((__half2*)g_B1)[base]     = __halves2half2(l[0], l[1]);
        ((__half2*)g_B1)[base + 1] = __halves2half2(l[2], l[3]);
    }
}

// ============================================================
// K1: fused fp16 m16n8k16 3-product GEMM (BM=64, BN=512, K=128)
//     with IN-KERNEL A limb conversion + epilogue (d assembly,
//     argmin over 513, move bits).
// A limbs: 8 resident k16-chunks, 48B rows. B: double-buffered.
// One sync per chunk (double buffering makes the tail sync redundant).
// ============================================================
#define E2S_OFF    0
#define AL_OFF     2176        // 8 chunks x (hi 3072B + lo 3072B) = 49152
#define ACH_STR    6144
#define ALO_OFF    3072
#define BS_OFF     51328       // 2 buf x (hi 24576B + lo 24576B) = 98304
#define BBUF_STR   49152
#define BLO_OFF    24576
#define AF32_OFF   149632      // transient 64x128 fp32 tile = 32768
#define SD_OFF     2176        // epilogue overlay (A/B tiles dead)
#define SD_STRIDE  536
#define SMEM_BYTES 182400

__global__ void __launch_bounds__(512, 1)
k_gemm_fused(const float* __restrict__ A, const float* __restrict__ E) {
    extern __shared__ char smem[];
    float* e2s = (float*)(smem + E2S_OFF);
    const uint32_t sb = smem_u32(smem);
    const int tid  = threadIdx.x;
    const int mb   = blockIdx.x;
    const int wid  = tid >> 5;
    const int lane = tid & 31;
    const int wm   = wid & 3;        // m strip (16 rows)
    const int wn   = wid >> 2;       // n strip (128 cols)
    const int g    = lane >> 2;      // group id 0..7
    const int cc   = lane & 3;       // thread in group

    // ---- B staging (chunk = 16 k-columns) ----
    auto stageB = [&](int c, int buf) {
        const int k0 = c * 16;
#pragma unroll
        for (int i = 0; i < 4; i++) {
            int e = tid + i * 512;
            int lim = e >> 10;
            int r = e & 1023;
            int n = r >> 1, q = r & 1;
            const __half* src = (lim ? g_B1 : g_B0) +
                                (size_t)n * 128 + k0 + q * 8;
            cpa16(sb + BS_OFF + buf * BBUF_STR + lim * BLO_OFF +
                      (uint32_t)(n * 48 + q * 16), src);
        }
        cpa_commit();
    };

    // ---- group 0: A fp32 tile (32KB, contiguous rows) ----
    {
        const float* Abase = A + (size_t)mb * 64 * 128;
#pragma unroll
        for (int i = 0; i < 4; i++) {
            int e = tid + i * 512;      // 16B piece index, 0..2047
            cpa16(sb + AF32_OFF + (uint32_t)e * 16, Abase + e * 4);
        }
        cpa_commit();
    }
    // ---- group 1: B chunk 0 ----
    stageB(0, 0);

    for (int i = tid; i < NCODE; i += 512) e2s[i] = g_e2[i];

    // ---- wait for A (B0 may still be in flight), convert to limbs ----
    cpa_wait1();
    __syncthreads();
    {
        const float2* Af = (const float2*)(smem + AF32_OFF);
#pragma unroll
        for (int it = 0; it < 8; it++) {
            int e = tid + it * 512;     // half2-pair index, 0..4095
            int m = e >> 6, j = e & 63; // row, k-pair (k = 2j)
            float2 v = Af[m * 64 + j];
            __half hx = __float2half_rn(v.x), hy = __float2half_rn(v.y);
            __half lx = __float2half_rn(v.x - __half2float(hx));
            __half ly = __float2half_rn(v.y - __half2float(hy));
            uint32_t off = (uint32_t)(AL_OFF + (j >> 3) * ACH_STR +
                                      m * 48 + (j & 7) * 4);
            *(__half2*)(smem + off)           = __halves2half2(hx, hy);
            *(__half2*)(smem + off + ALO_OFF) = __halves2half2(lx, ly);
        }
    }

    float acc[16][4];
#pragma unroll
    for (int i = 0; i < 16; i++)
#pragma unroll
        for (int j = 0; j < 4; j++) acc[i][j] = 0.0f;

    for (int c = 0; c < 8; c++) {
        cpa_wait0();
        __syncthreads();               // covers limb conversion (c=0) and
                                       // prior-chunk reads vs this buffer reuse
        if (c < 7) stageB(c + 1, (c + 1) & 1);

        // A limbs resident per chunk; halfs, row stride 24 halfs (48B)
        const __half* A0 = (const __half*)(smem + AL_OFF + c * ACH_STR);
        const __half* A1 = A0 + 1536;   // ALO_OFF bytes
        const __half* B0 = (const __half*)(smem + BS_OFF + (c & 1) * BBUF_STR);
        const __half* B1 = B0 + 12288;  // BLO_OFF bytes

        unsigned ah[4], al[4];
        {
            const int r0 = (wm * 16 + g) * 24;
            const int r8 = (wm * 16 + g + 8) * 24;
            ah[0] = *(const unsigned*)(A0 + r0 + 2 * cc);
            ah[1] = *(const unsigned*)(A0 + r8 + 2 * cc);
            ah[2] = *(const unsigned*)(A0 + r0 + 2 * cc + 8);
            ah[3] = *(const unsigned*)(A0 + r8 + 2 * cc + 8);
            al[0] = *(const unsigned*)(A1 + r0 + 2 * cc);
            al[1] = *(const unsigned*)(A1 + r8 + 2 * cc);
            al[2] = *(const unsigned*)(A1 + r0 + 2 * cc + 8);
            al[3] = *(const unsigned*)(A1 + r8 + 2 * cc + 8);
        }
#pragma unroll
        for (int nb = 0; nb < 16; nb++) {
            const int nrow = (wn * 128 + nb * 8 + g) * 24;
            unsigned bh0 = *(const unsigned*)(B0 + nrow + 2 * cc);
            unsigned bh1 = *(const unsigned*)(B0 + nrow + 2 * cc + 8);
            unsigned bl0 = *(const unsigned*)(B1 + nrow + 2 * cc);
            unsigned bl1 = *(const unsigned*)(B1 + nrow + 2 * cc + 8);
            mma16(acc[nb], ah, bh0, bh1);   // A_hi * B_hi
            mma16(acc[nb], ah, bl0, bl1);   // A_hi * B_lo
            mma16(acc[nb], al, bh0, bh1);   // A_lo * B_hi
        }
        // no tail sync: next iteration's wait+sync provides ordering;
        // stage(c+1) writes the other buffer.
    }
    __syncthreads();   // all warps done reading tiles before sd overlays them

    // ---- dump acc fragments to smem d-buffer (overlays tiles) ----
    float* sd = (float*)(smem + SD_OFF);
    {
        const int row0 = wm * 16 + g;
#pragma unroll
        for (int nb = 0; nb < 16; nb++) {
            const int col = wn * 128 + nb * 8 + 2 * cc;
            *(float2*)&sd[(size_t)row0 * SD_STRIDE + col] =
                make_float2(acc[nb][0], acc[nb][1]);
            *(float2*)&sd[(size_t)(row0 + 8) * SD_STRIDE + col] =
                make_float2(acc[nb][2], acc[nb][3]);
        }
    }
    __syncthreads();

    // ---- row scan: 8 threads per row, strided cols ----
    const int t   = tid & 7;
    const int rid = tid >> 3;
    const int row_g = mb * 64 + rid;

    // ks2 + dot with code 512 (fp32 from original inputs)
    float ks2 = 0.0f, dt = 0.0f;
    {
        const float4* kr = (const float4*)A + (size_t)row_g * 32;
        const float4* er = (const float4*)E + (size_t)512 * 32;
#pragma unroll
        for (int j = 0; j < 4; j++) {
            float4 a = kr[t * 4 + j];
            float4 e = __ldg(&er[t * 4 + j]);
            ks2 = fmaf(a.x, a.x, ks2); ks2 = fmaf(a.y, a.y, ks2);
            ks2 = fmaf(a.z, a.z, ks2); ks2 = fmaf(a.w, a.w, ks2);
            dt  = fmaf(a.x, e.x, dt);  dt  = fmaf(a.y, e.y, dt);
            dt  = fmaf(a.z, e.z, dt);  dt  = fmaf(a.w, e.w, dt);
        }
#pragma unroll
        for (int o = 1; o < 8; o <<= 1) {
            ks2 += __shfl_xor_sync(0xffffffffu, ks2, o);
            dt  += __shfl_xor_sync(0xffffffffu, dt, o);
        }
    }
    float d512 = (ks2 + e2s[512]) - 2.0f * dt;

    // dot' = 512*dot  =>  2*dot = dot' * (1/256), exact power-of-2 rescale
    const float RS = 1.0f / 256.0f;
    const float* sdr = sd + (size_t)rid * SD_STRIDE;
    float best = 3.4e38f;
    int   bi = 0;
    float dprev = 0.0f;
    unsigned word = 0;
    const unsigned shift = (unsigned)(tid & 24);  // 8 * (lane group)
#pragma unroll 4
    for (int k = 0; k < 64; k++) {
        float d = (ks2 + e2s[8 * k + t]) - RS * sdr[8 * k + t];
        if (k > 0) {
            float dnb = __shfl_down_sync(0xffffffffu, dprev, 1, 8);
            float d0  = __shfl_sync(0xffffffffu, d, 0, 8);
            float nxt = (t == 7) ? d0 : dnb;
            unsigned Bb = __ballot_sync(0xffffffffu, dprev > nxt);
            word |= ((Bb >> shift) & 0xFFu) << (((k - 1) & 3) * 8);
            if (((k - 1) & 3) == 3) {
                if (t == 0) g_move[(size_t)row_g * 16 + ((k - 1) >> 2)] = word;
                word = 0;
            }
        }
        if (d < best) { best = d; bi = 8 * k + t; }
        dprev = d;
    }
    {
        float dnb = __shfl_down_sync(0xffffffffu, dprev, 1, 8);
        unsigned Bb = __ballot_sync(0xffffffffu, (t < 7) && (dprev > dnb));
        word |= ((Bb >> shift) & 0xFFu) << 24;
        if (t == 0) g_move[(size_t)row_g * 16 + 15] = word;
    }
#pragma unroll
    for (int o = 1; o < 8; o <<= 1) {
        float ov = __shfl_xor_sync(0xffffffffu, best, o);
        int   oi = __shfl_xor_sync(0xffffffffu, bi, o);
        if (ov < best || (ov == best && oi < bi)) { best = ov; bi = oi; }
    }
    if (d512 < best) bi = 512;
    if (t == 0) g_minidx[row_g] = bi;
}

// ============================================================
// K3a: chunk transition tables (fully unrolled dependent chain)
// ============================================================
__global__ __launch_bounds__(512) void k_scantbl(void) {
    const int c   = blockIdx.x;     // 0..14
    const int b   = blockIdx.y;
    const int tid = threadIdx.x;
    __shared__ unsigned mw[64][16];
    const int t0 = c * 64 + 1;
#pragma unroll
    for (int r = 0; r < 2; r++) {
        int i = tid + r * 512;
        mw[i >> 4][i & 15] =
            g_move[(size_t)(b * 1024 + t0 + (i >> 4)) * 16 + (i & 15)];
    }
    __syncthreads();
    int ind = tid;
#pragma unroll
    for (int s = 0; s < 64; s++) ind += (mw[s][ind >> 5] >> (ind & 31)) & 1;
    g_tbl[((size_t)b * 15 + c) * 512 + tid] = (unsigned short)ind;
}

// ============================================================
// K3c: emit enc. One block per batch (grid 64 x 1024 threads).
// All 15 tables + the batch's full move-bit array live in smem:
// entry chase = 15 x ~30cyc LDS; each thread emits one position
// (chain <= 63 dependent LDS).
// ============================================================
#define EMIT_MW_WORDS (1023 * 16)            // 65472 B
#define EMIT_TBL_OFF  (EMIT_MW_WORDS * 4)    // u16 tables after mw
#define EMIT_SMEM     (EMIT_TBL_OFF + 15 * 512 * 2)   // 80832 B

__global__ __launch_bounds__(1024)
void k_emit_enc(const unsigned char* __restrict__ mask) {
    extern __shared__ char esm[];
    unsigned* mw = (unsigned*)esm;                          // [1023][16]
    unsigned short* tb = (unsigned short*)(esm + EMIT_TBL_OFF); // [15][512]
    __shared__ int ent[16];
    const int b   = blockIdx.x;
    const int tid = threadIdx.x;

    for (int i = tid; i < EMIT_MW_WORDS; i += 1024)
        mw[i] = g_move[(size_t)(b * 1024 + 1 + (i >> 4)) * 16 + (i & 15)];
    for (int i = tid; i < 15 * 512; i += 1024)
        tb[i] = g_tbl[(size_t)b * 15 * 512 + i];
    __syncthreads();

    if (tid == 0) {
        int ind = g_minidx[b * 1024];
        if (ind > 511) ind = 511;
        if (mask[b]) ind = 0;
        ent[0] = ind;
        for (int c = 0; c < 15; c++) {
            ind = tb[c * 512 + ind];
            ent[c + 1] = ind;
        }
    }
    __syncthreads();

    const int cl = tid >> 6;        // chunk 0..15
    const int s  = tid & 63;        // position in chunk
    int ind = ent[cl];
    for (int ss = 0; ss < s; ss++) {
        int r = cl * 64 + ss;       // move row (transition t = r+1)
        ind += (mw[r * 16 + (ind >> 5)] >> (ind & 31)) & 1;
    }
    g_enc[b * 1024 + tid] = ind;
}

// ============================================================
// K4: fused gathers + losses + key_hard + energy. Warp per (b,t).
// ============================================================
__global__ __launch_bounds__(256) void k_final(const float* __restrict__ ks,
                                               const float* __restrict__ emb,
                                               float* __restrict__ out) {
    const int row  = blockIdx.x * 8 + (threadIdx.x >> 5);
    const int lane = threadIdx.x & 31;
    const float4* k4 = (const float4*)ks + (size_t)row * 32;
    const float4* e4 = (const float4*)emb;

    int here = g_enc[row];
    int nxt  = here + 1; if (nxt > 511) nxt = 511;
    int mi   = g_minidx[row];

    float4 a  = k4[lane];
    float4 eh = e4[(size_t)here * 32 + lane];
    float4 en = e4[(size_t)nxt * 32 + lane];
    float4 em = e4[(size_t)mi * 32 + lane];

    float sh, sn, sm;
    {
        float d0 = a.x - eh.x, d1 = a.y - eh.y, d2 = a.z - eh.z, d3 = a.w - eh.w;
        sh = d0 * d0; sh = fmaf(d1, d1, sh); sh = fmaf(d2, d2, sh); sh = fmaf(d3, d3, sh);
    }
    {
        float d0 = a.x - en.x, d1 = a.y - en.y, d2 = a.z - en.z, d3 = a.w - en.w;
        sn = d0 * d0; sn = fmaf(d1, d1, sn); sn = fmaf(d2, d2, sn); sn = fmaf(d3, d3, sn);
    }
    {
        float d0 = a.x - em.x, d1 = a.y - em.y, d2 = a.z - em.z, d3 = a.w - em.w;
        sm = d0 * d0; sm = fmaf(d1, d1, sm); sm = fmaf(d2, d2, sm); sm = fmaf(d3, d3, sm);
    }
#pragma unroll
    for (int off = 16; off; off >>= 1) {
        sh += __shfl_xor_sync(0xffffffffu, sh, off);
        sn += __shfl_xor_sync(0xffffffffu, sn, off);
        sm += __shfl_xor_sync(0xffffffffu, sm, off);
    }

    float4 o;
    o.x = a.x + (eh.x - a.x);
    o.y = a.y + (eh.y - a.y);
    o.z = a.z + (eh.z - a.z);
    o.w = a.w + (eh.w - a.w);
    ((float4*)(out + OFF_KH))[(size_t)row * 32 + lane] = o;

    if (lane == 0) {
        float Lh = sh + sh * 0.2f;
        float Ln = sn + sn * 0.2f;
        float Lm = sm + sm * 0.2f;
        float dif = sn - sh;
        float energy = dif + dif * 0.2f;
        float lmh = (Lm < Lh) ? Lm : 0.0f;
        float lmn = (Lm < Ln) ? Lm : 0.0f;
        out[OFF_LH  + row] = (Lh - Ln) - lmh;
        out[OFF_LNX + row] = (Ln - Lh) - lmn;
        out[OFF_ENC + row] = (float)here;
        g_energy[row] = energy;
    }
}

// ============================================================
// K5: per-batch reductions
// ============================================================
__global__ __launch_bounds__(256) void k_reduce_b(void) {
    const int b   = blockIdx.x;
    const int tid = threadIdx.x;
    __shared__ float sE[256], sL[256];
    __shared__ int   sMn[256], sMx[256];
    const float* eb = g_energy + b * 1024;
    const int*   cb = g_enc + b * 1024;

    float aE = 0.0f, aL = 0.0f;
    int mn = 1 << 30, mx = -1;
    for (int t = tid; t < 1024; t += 256) {
        aE += eb[t];
        int cv = cb[t];
        mn = min(mn, cv);
        mx = max(mx, cv);
    }
    const float EPS = (float)(1e-6 / 512.0);
    for (int t = tid + 1; t < 1024; t += 256) {
        float ch = (cb[t] != cb[t - 1]) ? 0.0f : (eb[t] - eb[t - 1]);
        aL += fmaxf(ch + EPS, 0.0f);
    }
    sE[tid] = aE; sL[tid] = aL; sMn[tid] = mn; sMx[tid] = mx;
    __syncthreads();
    for (int s = 128; s; s >>= 1) {
        if (tid < s) {
            sE[tid] += sE[tid + s];
            sL[tid] += sL[tid + s];
            sMn[tid] = min(sMn[tid], sMn[tid + s]);
            sMx[tid] = max(sMx[tid], sMx[tid + s]);
        }
        __syncthreads();
    }
    if (tid == 0) {
        g_pE[b]  = sE[0];
        g_pL[b]  = sL[0];
        g_rng[b] = sMx[0] - sMn[0];
    }
}

// ============================================================
// K6: final scalars
// ============================================================
__global__ void k_scalars(float* __restrict__ out) {
    int tid = threadIdx.x;  // 64
    __shared__ float sE[64], sL[64];
    __shared__ int   sR[64];
    sE[tid] = g_pE[tid]; sL[tid] = g_pL[tid]; sR[tid] = g_rng[tid];
    __syncthreads();
    for (int s = 32; s; s >>= 1) {
        if (tid < s) {
            sE[tid] += sE[tid + s];
            sL[tid] += sL[tid + s];
            sR[tid] = max(sR[tid], sR[tid + s]);
        }
        __syncthreads();
    }
    if (tid == 0) {
        out[OFF_EM]  = sE[0] / 65536.0f;
        out[OFF_LED] = sL[0] / 65472.0f;
        out[OFF_V]   = (float)sR[0];
    }
}

// ============================================================
extern "C" void kernel_launch(void* const* d_in, const int* in_sizes, int n_in,
                              void* d_out, int out_size) {
    const float* ks = nullptr;
    const float* emb = nullptr;
    const unsigned char* mask = nullptr;
    for (int i = 0; i < n_in; i++) {
        if (in_sizes[i] == ROWS * D_)        ks   = (const float*)d_in[i];
        else if (in_sizes[i] == NCODE * D_)  emb  = (const float*)d_in[i];
        else if (in_sizes[i] == B_)          mask = (const unsigned char*)d_in[i];
    }
    float* out = (float*)d_out;

    cudaFuncSetAttribute(k_gemm_fused,
                         cudaFuncAttributeMaxDynamicSharedMemorySize, SMEM_BYTES);
    cudaFuncSetAttribute(k_emit_enc,
                         cudaFuncAttributeMaxDynamicSharedMemorySize, EMIT_SMEM);

    k_split_b<<<(NCODE * 32 + 255) / 256, 256>>>(emb);
    k_gemm_fused<<<ROWS / 64, 512, SMEM_BYTES>>>(ks, emb);
    k_scantbl<<<dim3(15, B_), 512>>>();
    k_emit_enc<<<B_, 1024, EMIT_SMEM>>>(mask);
    k_final<<<ROWS / 8, 256>>>(ks, emb, out);
    k_reduce_b<<<B_, 256>>>();
    k_scalars<<<1, 64>>>(out);
}

// round 16
// speedup vs baseline: 2.4271x; 1.0202x over previous
#include <cuda_runtime.h>
#include <cuda_fp16.h>
#include <cstdint>

typedef unsigned long long ull;

#define B_    64
#define T_    1024
#define D_    128
#define NE    512
#define NCODE 513
#define ROWS  (B_ * T_)   // 65536

// ---- output layout (float32, tuple order) ----
#define OFF_KH  0
#define OFF_ENC 8388608
#define OFF_V   8454144
#define OFF_LH  8454145
#define OFF_LNX 8519681
#define OFF_EM  8585217
#define OFF_LED 8585218

// ---- scratch ----
__device__ __half         g_B0[(size_t)NE * D_];     // fp16 hi limb of 512*emb [n][k]
__device__ __half         g_B1[(size_t)NE * D_];     // fp16 lo limb
__device__ float          g_e2[NCODE];
__device__ int            g_minidx[ROWS];
__device__ __align__(16) unsigned g_move[(size_t)ROWS * 16];
__device__ unsigned short g_tbl[(size_t)B_ * 15 * 512];
__device__ int            g_ent[B_ * 16];
__device__ int            g_enc[ROWS];
__device__ float          g_energy[ROWS];
__device__ float          g_pE[B_], g_pL[B_];
__device__ int            g_rng[B_];

// ============================================================
// helpers
// ============================================================
__device__ __forceinline__ uint32_t smem_u32(const void* p) {
    uint32_t a;
    asm("{ .reg .u64 t; cvta.to.shared.u64 t, %1; cvt.u32.u64 %0, t; }"
        : "=r"(a) : "l"(p));
    return a;
}
__device__ __forceinline__ void cpa16(uint32_t dst, const void* src) {
    asm volatile("cp.async.ca.shared.global [%0], [%1], 16;"
                 :: "r"(dst), "l"(src));
}
__device__ __forceinline__ void cpa_commit(void) {
    asm volatile("cp.async.commit_group;");
}
__device__ __forceinline__ void cpa_wait0(void) {
    asm volatile("cp.async.wait_group 0;");
}
__device__ __forceinline__ void cpa_wait1(void) {
    asm volatile("cp.async.wait_group 1;");
}
__device__ __forceinline__ void mma16(float* d, const unsigned* a,
                                      unsigned b0, unsigned b1) {
    asm("mma.sync.aligned.m16n8k16.row.col.f32.f16.f16.f32 "
        "{%0,%1,%2,%3}, {%4,%5,%6,%7}, {%8,%9}, {%0,%1,%2,%3};"
        : "+f"(d[0]), "+f"(d[1]), "+f"(d[2]), "+f"(d[3])
        : "r"(a[0]), "r"(a[1]), "r"(a[2]), "r"(a[3]), "r"(b0), "r"(b1));
}

// ============================================================
// K-1b: per-row e2 for all 513 codes + fp16 limb split of 512*emb
//       (rows 0..511) into g_B0/g_B1 [n][k]. Warp per row.
// ============================================================
__global__ __launch_bounds__(256) void k_split_b(const float* __restrict__ emb) {
    int gw   = (blockIdx.x * 256 + threadIdx.x) >> 5;
    int lane = threadIdx.x & 31;
    if (gw >= NCODE) return;
    float4 v = ((const float4*)emb)[(size_t)gw * 32 + lane];
    float s = v.x * v.x;
    s = fmaf(v.y, v.y, s);
    s = fmaf(v.z, v.z, s);
    s = fmaf(v.w, v.w, s);
#pragma unroll
    for (int off = 16; off; off >>= 1) s += __shfl_xor_sync(0xffffffffu, s, off);
    if (lane == 0) g_e2[gw] = s;
    if (gw < NE) {
        const float* vp = &v.x;
        __half h[4], l[4];
#pragma unroll
        for (int q = 0; q < 4; q++) {
            float b = vp[q] * 512.0f;              // exact scaling
            h[q] = __float2half_rn(b);
            l[q] = __float2half_rn(b - __half2float(h[q]));
        }
        size_t base = (size_t)gw * 64 + lane * 2;  // half2 index
        ((__half2*)g_B0)[base]     = __halves2half2(h[0], h[1]);
        ((__half2*)g_B0)[base + 1] = __halves2half2(h[2], h[3]);
        ((__half2*)g_B1)[base]     = __halves2half2(l[0], l[1]);
        ((__half2*)g_B1)[base + 1] = __halves2half2(l[2], l[3]);
    }
}

// ============================================================
// K1: fused fp16 m16n8k16 3-product GEMM (BM=64, BN=512, K=128)
//     with IN-KERNEL A limb conversion + epilogue (d assembly,
//     argmin over 513, move bits; column-contiguous scan).
// d expression is byte-identical to the R10-13 passing kernels:
//     d = (ks2 + e2[j]) - RS * dot'[j]
// e2 served from a padded conflict-free smem copy (bit-identical values).
// ============================================================
#define E2S_OFF    0
#define AL_OFF     2176        // 8 chunks x (hi 3072B + lo 3072B) = 49152
#define ACH_STR    6144
#define ALO_OFF    3072
#define BS_OFF     51328       // 2 buf x (hi 24576B + lo 24576B) = 98304
#define BBUF_STR   49152
#define BLO_OFF    24576
#define AF32_OFF   149632      // transient 64x128 fp32 tile = 32768 (reused for e2p)
#define SD_OFF     2176        // epilogue overlay (A/B tiles dead)
#define SD_STRIDE  545         // == 1 (mod 32): conflict-free row spread
#define SMEM_BYTES 182400

__global__ void __launch_bounds__(512, 1)
k_gemm_fused(const float* __restrict__ A, const float* __restrict__ E) {
    extern __shared__ char smem[];
    float* e2s = (float*)(smem + E2S_OFF);
    const uint32_t sb = smem_u32(smem);
    const int tid  = threadIdx.x;
    const int mb   = blockIdx.x;
    const int wid  = tid >> 5;
    const int lane = tid & 31;
    const int wm   = wid & 3;        // m strip (16 rows)
    const int wn   = wid >> 2;       // n strip (128 cols)
    const int g    = lane >> 2;      // group id 0..7
    const int cc   = lane & 3;       // thread in group

    // ---- B staging (chunk = 16 k-columns) ----
    auto stageB = [&](int c, int buf) {
        const int k0 = c * 16;
#pragma unroll
        for (int i = 0; i < 4; i++) {
            int e = tid + i * 512;
            int lim = e >> 10;
            int r = e & 1023;
            int n = r >> 1, q = r & 1;
            const __half* src = (lim ? g_B1 : g_B0) +
                                (size_t)n * 128 + k0 + q * 8;
            cpa16(sb + BS_OFF + buf * BBUF_STR + lim * BLO_OFF +
                      (uint32_t)(n * 48 + q * 16), src);
        }
        cpa_commit();
    };

    // ---- group 0: A fp32 tile (32KB, contiguous rows) ----
    {
        const float* Abase = A + (size_t)mb * 64 * 128;
#pragma unroll
        for (int i = 0; i < 4; i++) {
            int e = tid + i * 512;      // 16B piece index, 0..2047
            cpa16(sb + AF32_OFF + (uint32_t)e * 16, Abase + e * 4);
        }
        cpa_commit();
    }
    // ---- group 1: B chunk 0 ----
    stageB(0, 0);

    for (int i = tid; i < NCODE; i += 512) e2s[i] = g_e2[i];

    // ---- wait for A (B0 may still be in flight), convert to limbs ----
    cpa_wait1();
    __syncthreads();
    {
        const float2* Af = (const float2*)(smem + AF32_OFF);
#pragma unroll
        for (int it = 0; it < 8; it++) {
            int e = tid + it * 512;     // half2-pair index, 0..4095
            int m = e >> 6, j = e & 63; // row, k-pair (k = 2j)
            float2 v = Af[m * 64 + j];
            __half hx = __float2half_rn(v.x), hy = __float2half_rn(v.y);
            __half lx = __float2half_rn(v.x - __half2float(hx));
            __half ly = __float2half_rn(v.y - __half2float(hy));
            uint32_t off = (uint32_t)(AL_OFF + (j >> 3) * ACH_STR +
                                      m * 48 + (j & 7) * 4);
            *(__half2*)(smem + off)           = __halves2half2(hx, hy);
            *(__half2*)(smem + off + ALO_OFF) = __halves2half2(lx, ly);
        }
    }

    float acc[16][4];
#pragma unroll
    for (int i = 0; i < 16; i++)
#pragma unroll
        for (int j = 0; j < 4; j++) acc[i][j] = 0.0f;

    for (int c = 0; c < 8; c++) {
        cpa_wait0();
        __syncthreads();
        if (c < 7) stageB(c + 1, (c + 1) & 1);

        const __half* A0 = (const __half*)(smem + AL_OFF + c * ACH_STR);
        const __half* A1 = A0 + 1536;   // ALO_OFF bytes
        const __half* B0 = (const __half*)(smem + BS_OFF + (c & 1) * BBUF_STR);
        const __half* B1 = B0 + 12288;  // BLO_OFF bytes

        unsigned ah[4], al[4];
        {
            const int r0 = (wm * 16 + g) * 24;
            const int r8 = (wm * 16 + g + 8) * 24;
            ah[0] = *(const unsigned*)(A0 + r0 + 2 * cc);
            ah[1] = *(const unsigned*)(A0 + r8 + 2 * cc);
            ah[2] = *(const unsigned*)(A0 + r0 + 2 * cc + 8);
            ah[3] = *(const unsigned*)(A0 + r8 + 2 * cc + 8);
            al[0] = *(const unsigned*)(A1 + r0 + 2 * cc);
            al[1] = *(const unsigned*)(A1 + r8 + 2 * cc);
            al[2] = *(const unsigned*)(A1 + r0 + 2 * cc + 8);
            al[3] = *(const unsigned*)(A1 + r8 + 2 * cc + 8);
        }
#pragma unroll
        for (int nb = 0; nb < 16; nb++) {
            const int nrow = (wn * 128 + nb * 8 + g) * 24;
            unsigned bh0 = *(const unsigned*)(B0 + nrow + 2 * cc);
            unsigned bh1 = *(const unsigned*)(B0 + nrow + 2 * cc + 8);
            unsigned bl0 = *(const unsigned*)(B1 + nrow + 2 * cc);
            unsigned bl1 = *(const unsigned*)(B1 + nrow + 2 * cc + 8);
            mma16(acc[nb], ah, bh0, bh1);   // A_hi * B_hi
            mma16(acc[nb], ah, bl0, bl1);   // A_hi * B_lo
            mma16(acc[nb], al, bh0, bh1);   // A_lo * B_hi
        }
    }
    __syncthreads();   // all warps done reading tiles before sd overlays them

    // ---- dump raw dot' to sd (scalar 4B stores; odd stride) ----
    // ---- + padded e2 copy into dead AF32 region (bit-identical values) ----
    float* sd  = (float*)(smem + SD_OFF);
    float* e2p = (float*)(smem + AF32_OFF);
    e2p[tid + ((tid >> 6) << 2)] = e2s[tid];     // tid 0..511 covers codes 0..511
    {
        const int row0 = wm * 16 + g;
#pragma unroll
        for (int nb = 0; nb < 16; nb++) {
            const int col  = wn * 128 + nb * 8 + 2 * cc;
            const int colp = col + ((col >> 6) << 2);   // +4 pad per 64 cols
            float* p0 = &sd[(size_t)row0 * SD_STRIDE + colp];
            float* p1 = &sd[(size_t)(row0 + 8) * SD_STRIDE + colp];
            p0[0] = acc[nb][0];
            p0[1] = acc[nb][1];
            p1[0] = acc[nb][2];
            p1[1] = acc[nb][3];
        }
    }
    __syncthreads();

    // ---- row scan: 8 threads/row, 64 CONSECUTIVE cols per thread ----
    const int t   = tid & 7;
    const int rid = tid >> 3;
    const int row_g = mb * 64 + rid;

    // ks2 + dot with code 512 (fp32 from original inputs)
    float ks2 = 0.0f, dt = 0.0f;
    {
        const float4* kr = (const float4*)A + (size_t)row_g * 32;
        const float4* er = (const float4*)E + (size_t)512 * 32;
#pragma unroll
        for (int j = 0; j < 4; j++) {
            float4 a = kr[t * 4 + j];
            float4 e = __ldg(&er[t * 4 + j]);
            ks2 = fmaf(a.x, a.x, ks2); ks2 = fmaf(a.y, a.y, ks2);
            ks2 = fmaf(a.z, a.z, ks2); ks2 = fmaf(a.w, a.w, ks2);
            dt  = fmaf(a.x, e.x, dt);  dt  = fmaf(a.y, e.y, dt);
            dt  = fmaf(a.z, e.z, dt);  dt  = fmaf(a.w, e.w, dt);
        }
#pragma unroll
        for (int o = 1; o < 8; o <<= 1) {
            ks2 += __shfl_xor_sync(0xffffffffu, ks2, o);
            dt  += __shfl_xor_sync(0xffffffffu, dt, o);
        }
    }
    float d512 = (ks2 + e2s[512]) - 2.0f * dt;

    // dot' = 512*dot  =>  2*dot = dot'/256, exact power-of-2 rescale
    const float RS = 1.0f / 256.0f;
    const float* sdr = sd + (size_t)rid * SD_STRIDE + t * 68;
    const float* e2r = e2p + t * 68;
    const int jbase = t * 64;
    float best = 3.4e38f;
    int   bi = 0;
    float dprev = 0.0f, dfirst = 0.0f;
    unsigned w0 = 0, w1 = 0;
#pragma unroll
    for (int i = 0; i < 64; i++) {
        float d = (ks2 + e2r[i]) - RS * sdr[i];   // identical shape to R10-13
        if (i == 0) {
            dfirst = d;
        } else {
            unsigned bit = (dprev > d) ? 1u : 0u;
            const int p = i - 1;
            if (p < 32) w0 |= bit << p;
            else        w1 |= bit << (p - 32);
        }
        if (d < best) { best = d; bi = jbase + i; }
        dprev = d;
    }
    {
        float nf = __shfl_down_sync(0xffffffffu, dfirst, 1, 8);
        unsigned bitb = ((t < 7) && (dprev > nf)) ? 1u : 0u;
        w1 |= bitb << 31;
    }
    *(ull*)&g_move[(size_t)row_g * 16 + 2 * t] = (ull)w0 | ((ull)w1 << 32);

#pragma unroll
    for (int o = 1; o < 8; o <<= 1) {
        float ov = __shfl_xor_sync(0xffffffffu, best, o);
        int   oi = __shfl_xor_sync(0xffffffffu, bi, o);
        if (ov < best || (ov == best && oi < bi)) { best = ov; bi = oi; }
    }
    if (d512 < best) bi = 512;
    if (t == 0) g_minidx[row_g] = bi;
}

// ============================================================
// K3a: chunk transition tables (fully unrolled dependent chain)
// ============================================================
__global__ __launch_bounds__(512) void k_scantbl(void) {
    const int c   = blockIdx.x;     // 0..14
    const int b   = blockIdx.y;
    const int tid = threadIdx.x;
    __shared__ unsigned mw[64][16];
    const int t0 = c * 64 + 1;
#pragma unroll
    for (int r = 0; r < 2; r++) {
        int i = tid + r * 512;
        mw[i >> 4][i & 15] =
            g_move[(size_t)(b * 1024 + t0 + (i >> 4)) * 16 + (i & 15)];
    }
    __syncthreads();
    int ind = tid;
#pragma unroll
    for (int s = 0; s < 64; s++) ind += (mw[s][ind >> 5] >> (ind & 31)) & 1;
    g_tbl[((size_t)b * 15 + c) * 512 + tid] = (unsigned short)ind;
}

// ============================================================
// K3b: entry states. One block per batch (64 SMs in parallel);
// thread 0 walks 15 L2-hot tables (~2us total).
// ============================================================
__global__ __launch_bounds__(32) void k_entries(const unsigned char* __restrict__ mask) {
    if (threadIdx.x != 0) return;
    const int b = blockIdx.x;
    int ind = g_minidx[b * 1024];
    if (ind > 511) ind = 511;
    if (mask[b]) ind = 0;
    g_ent[b * 16] = ind;
    for (int c = 0; c < 15; c++) {
        ind = g_tbl[((size_t)b * 15 + c) * 512 + ind];
        g_ent[b * 16 + c + 1] = ind;
    }
}

// ============================================================
// K3c: emit enc. grid (16, 64) x 64 threads, 4KB smem/block,
// entry state precomputed -> no table walk on the critical path.
// ============================================================
__global__ __launch_bounds__(64) void k_emit_enc(void) {
    const int c   = blockIdx.x;     // 0..15
    const int b   = blockIdx.y;
    const int tid = threadIdx.x;
    __shared__ unsigned mw[63][16];
    const int t0 = c * 64 + 1;
    for (int i = tid; i < 63 * 16; i += 64)
        mw[i >> 4][i & 15] =
            g_move[(size_t)(b * 1024 + t0 + (i >> 4)) * 16 + (i & 15)];
    __syncthreads();
    int ind = g_ent[b * 16 + c];
    for (int s = 0; s < tid; s++) ind += (mw[s][ind >> 5] >> (ind & 31)) & 1;
    g_enc[b * 1024 + c * 64 + tid] = ind;
}

// ============================================================
// K4: fused gathers + losses + key_hard + energy. Warp per (b,t).
// ============================================================
__global__ __launch_bounds__(256) void k_final(const float* __restrict__ ks,
                                               const float* __restrict__ emb,
                                               float* __restrict__ out) {
    const int row  = blockIdx.x * 8 + (threadIdx.x >> 5);
    const int lane = threadIdx.x & 31;
    const float4* k4 = (const float4*)ks + (size_t)row * 32;
    const float4* e4 = (const float4*)emb;

    int here = g_enc[row];
    int nxt  = here + 1; if (nxt > 511) nxt = 511;
    int mi   = g_minidx[row];

    float4 a  = k4[lane];
    float4 eh = e4[(size_t)here * 32 + lane];
    float4 en = e4[(size_t)nxt * 32 + lane];
    float4 em = e4[(size_t)mi * 32 + lane];

    float sh, sn, sm;
    {
        float d0 = a.x - eh.x, d1 = a.y - eh.y, d2 = a.z - eh.z, d3 = a.w - eh.w;
        sh = d0 * d0; sh = fmaf(d1, d1, sh); sh = fmaf(d2, d2, sh); sh = fmaf(d3, d3, sh);
    }
    {
        float d0 = a.x - en.x, d1 = a.y - en.y, d2 = a.z - en.z, d3 = a.w - en.w;
        sn = d0 * d0; sn = fmaf(d1, d1, sn); sn = fmaf(d2, d2, sn); sn = fmaf(d3, d3, sn);
    }
    {
        float d0 = a.x - em.x, d1 = a.y - em.y, d2 = a.z - em.z, d3 = a.w - em.w;
        sm = d0 * d0; sm = fmaf(d1, d1, sm); sm = fmaf(d2, d2, sm); sm = fmaf(d3, d3, sm);
    }
#pragma unroll
    for (int off = 16; off; off >>= 1) {
        sh += __shfl_xor_sync(0xffffffffu, sh, off);
        sn += __shfl_xor_sync(0xffffffffu, sn, off);
        sm += __shfl_xor_sync(0xffffffffu, sm, off);
    }

    float4 o;
    o.x = a.x + (eh.x - a.x);
    o.y = a.y + (eh.y - a.y);
    o.z = a.z + (eh.z - a.z);
    o.w = a.w + (eh.w - a.w);
    ((float4*)(out + OFF_KH))[(size_t)row * 32 + lane] = o;

    if (lane == 0) {
        float Lh = sh + sh * 0.2f;
        float Ln = sn + sn * 0.2f;
        float Lm = sm + sm * 0.2f;
        float dif = sn - sh;
        float energy = dif + dif * 0.2f;
        float lmh = (Lm < Lh) ? Lm : 0.0f;
        float lmn = (Lm < Ln) ? Lm : 0.0f;
        out[OFF_LH  + row] = (Lh - Ln) - lmh;
        out[OFF_LNX + row] = (Ln - Lh) - lmn;
        out[OFF_ENC + row] = (float)here;
        g_energy[row] = energy;
    }
}

// ============================================================
// K5: per-batch reductions
// ============================================================
__global__ __launch_bounds__(256) void k_reduce_b(void) {
    const int b   = blockIdx.x;
    const int tid = threadIdx.x;
    __shared__ float sE[256], sL[256];
    __shared__ int   sMn[256], sMx[256];
    const float* eb = g_energy + b * 1024;
    const int*   cb = g_enc + b * 1024;

    float aE = 0.0f, aL = 0.0f;
    int mn = 1 << 30, mx = -1;
    for (int t = tid; t < 1024; t += 256) {
        aE += eb[t];
        int cv = cb[t];
        mn = min(mn, cv);
        mx = max(mx, cv);
    }
    const float EPS = (float)(1e-6 / 512.0);
    for (int t = tid + 1; t < 1024; t += 256) {
        float ch = (cb[t] != cb[t - 1]) ? 0.0f : (eb[t] - eb[t - 1]);
        aL += fmaxf(ch + EPS, 0.0f);
    }
    sE[tid] = aE; sL[tid] = aL; sMn[tid] = mn; sMx[tid] = mx;
    __syncthreads();
    for (int s = 128; s; s >>= 1) {
        if (tid < s) {
            sE[tid] += sE[tid + s];
            sL[tid] += sL[tid + s];
            sMn[tid] = min(sMn[tid], sMn[tid + s]);
            sMx[tid] = max(sMx[tid], sMx[tid + s]);
        }
        __syncthreads();
    }
    if (tid == 0) {
        g_pE[b]  = sE[0];
        g_pL[b]  = sL[0];
        g_rng[b] = sMx[0] - sMn[0];
    }
}

// ============================================================
// K6: final scalars
// ============================================================
__global__ void k_scalars(float* __restrict__ out) {
    int tid = threadIdx.x;  // 64
    __shared__ float sE[64], sL[64];
    __shared__ int   sR[64];
    sE[tid] = g_pE[tid]; sL[tid] = g_pL[tid]; sR[tid] = g_rng[tid];
    __syncthreads();
    for (int s = 32; s; s >>= 1) {
        if (tid < s) {
            sE[tid] += sE[tid + s];
            sL[tid] += sL[tid + s];
            sR[tid] = max(sR[tid], sR[tid + s]);
        }
        __syncthreads();
    }
    if (tid == 0) {
        out[OFF_EM]  = sE[0] / 65536.0f;
        out[OFF_LED] = sL[0] / 65472.0f;
        out[OFF_V]   = (float)sR[0];
    }
}

// ============================================================
extern "C" void kernel_launch(void* const* d_in, const int* in_sizes, int n_in,
                              void* d_out, int out_size) {
    const float* ks = nullptr;
    const float* emb = nullptr;
    const unsigned char* mask = nullptr;
    for (int i = 0; i < n_in; i++) {
        if (in_sizes[i] == ROWS * D_)        ks   = (const float*)d_in[i];
        else if (in_sizes[i] == NCODE * D_)  emb  = (const float*)d_in[i];
        else if (in_sizes[i] == B_)          mask = (const unsigned char*)d_in[i];
    }
    float* out = (float*)d_out;

    cudaFuncSetAttribute(k_gemm_fused,
                         cudaFuncAttributeMaxDynamicSharedMemorySize, SMEM_BYTES);

    k_split_b<<<(NCODE * 32 + 255) / 256, 256>>>(emb);
    k_gemm_fused<<<ROWS / 64, 512, SMEM_BYTES>>>(ks, emb);
    k_scantbl<<<dim3(15, B_), 512>>>();
    k_entries<<<B_, 32>>>(mask);
    k_emit_enc<<<dim3(16, B_), 64>>>();
    k_final<<<ROWS / 8, 256>>>(ks, emb, out);
    k_reduce_b<<<B_, 256>>>();
    k_scalars<<<1, 64>>>(out);
}

// round 17
// speedup vs baseline: 2.4491x; 1.0091x over previous
#include <cuda_runtime.h>
#include <cuda_fp16.h>
#include <cstdint>

typedef unsigned long long ull;

#define B_    64
#define T_    1024
#define D_    128
#define NE    512
#define NCODE 513
#define ROWS  (B_ * T_)   // 65536

// ---- output layout (float32, tuple order) ----
#define OFF_KH  0
#define OFF_ENC 8388608
#define OFF_V   8454144
#define OFF_LH  8454145
#define OFF_LNX 8519681
#define OFF_EM  8585217
#define OFF_LED 8585218

// ---- scratch ----
__device__ __half         g_B0[(size_t)NE * D_];     // fp16 hi limb of 512*emb [n][k]
__device__ __half         g_B1[(size_t)NE * D_];     // fp16 lo limb
__device__ float          g_e2[NCODE];
__device__ int            g_minidx[ROWS];
__device__ __align__(16) unsigned g_move[(size_t)ROWS * 16];
__device__ unsigned short g_tbl[(size_t)B_ * 15 * 512];
__device__ int            g_ent[B_ * 16];
__device__ int            g_enc[ROWS];
__device__ float          g_energy[ROWS];
__device__ float          g_pE[B_], g_pL[B_];
__device__ int            g_rng[B_];

// ============================================================
// helpers
// ============================================================
__device__ __forceinline__ uint32_t smem_u32(const void* p) {
    uint32_t a;
    asm("{ .reg .u64 t; cvta.to.shared.u64 t, %1; cvt.u32.u64 %0, t; }"
        : "=r"(a) : "l"(p));
    return a;
}
__device__ __forceinline__ void cpa16(uint32_t dst, const void* src) {
    asm volatile("cp.async.ca.shared.global [%0], [%1], 16;"
                 :: "r"(dst), "l"(src));
}
__device__ __forceinline__ void cpa_commit(void) {
    asm volatile("cp.async.commit_group;");
}
__device__ __forceinline__ void cpa_wait0(void) {
    asm volatile("cp.async.wait_group 0;");
}
__device__ __forceinline__ void cpa_wait1(void) {
    asm volatile("cp.async.wait_group 1;");
}
__device__ __forceinline__ void mma16(float* d, const unsigned* a,
                                      unsigned b0, unsigned b1) {
    asm("mma.sync.aligned.m16n8k16.row.col.f32.f16.f16.f32 "
        "{%0,%1,%2,%3}, {%4,%5,%6,%7}, {%8,%9}, {%0,%1,%2,%3};"
        : "+f"(d[0]), "+f"(d[1]), "+f"(d[2]), "+f"(d[3])
        : "r"(a[0]), "r"(a[1]), "r"(a[2]), "r"(a[3]), "r"(b0), "r"(b1));
}

// ============================================================
// K-1b: per-row e2 for all 513 codes + fp16 limb split of 512*emb
//       (rows 0..511) into g_B0/g_B1 [n][k]. Warp per row.
// ============================================================
__global__ __launch_bounds__(256) void k_split_b(const float* __restrict__ emb) {
    int gw   = (blockIdx.x * 256 + threadIdx.x) >> 5;
    int lane = threadIdx.x & 31;
    if (gw >= NCODE) return;
    float4 v = ((const float4*)emb)[(size_t)gw * 32 + lane];
    float s = v.x * v.x;
    s = fmaf(v.y, v.y, s);
    s = fmaf(v.z, v.z, s);
    s = fmaf(v.w, v.w, s);
#pragma unroll
    for (int off = 16; off; off >>= 1) s += __shfl_xor_sync(0xffffffffu, s, off);
    if (lane == 0) g_e2[gw] = s;
    if (gw < NE) {
        const float* vp = &v.x;
        __half h[4], l[4];
#pragma unroll
        for (int q = 0; q < 4; q++) {
            float b = vp[q] * 512.0f;              // exact scaling
            h[q] = __float2half_rn(b);
            l[q] = __float2half_rn(b - __half2float(h[q]));
        }
        size_t base = (size_t)gw * 64 + lane * 2;  // half2 index
        ((__half2*)g_B0)[base]     = __halves2half2(h[0], h[1]);
        ((__half2*)g_B0)[base + 1] = __halves2half2(h[2], h[3]);
        ((__half2*)g_B1)[base]     = __halves2half2(l[0], l[1]);
        ((__half2*)g_B1)[base + 1] = __halves2half2(l[2], l[3]);
    }
}

// ============================================================
// K1: fused fp16 m16n8k16 3-product GEMM (BM=64, BN=512, K=128)
//     with IN-KERNEL A limb conversion + epilogue (d assembly,
//     argmin over 513, move bits; column-contiguous scan).
// d expression is byte-identical to the R10-13 passing kernels:
//     d = (ks2 + e2[j]) - RS * dot'[j]
// e2 served from a padded conflict-free smem copy (bit-identical values).
// ============================================================
#define E2S_OFF    0
#define AL_OFF     2176        // 8 chunks x (hi 3072B + lo 3072B) = 49152
#define ACH_STR    6144
#define ALO_OFF    3072
#define BS_OFF     51328       // 2 buf x (hi 24576B + lo 24576B) = 98304
#define BBUF_STR   49152
#define BLO_OFF    24576
#define AF32_OFF   149632      // transient 64x128 fp32 tile = 32768 (reused for e2p)
#define SD_OFF     2176        // epilogue overlay (A/B tiles dead)
#define SD_STRIDE  545         // == 1 (mod 32): conflict-free row spread
#define SMEM_BYTES 182400

__global__ void __launch_bounds__(512, 1)
k_gemm_fused(const float* __restrict__ A, const float* __restrict__ E) {
    extern __shared__ char smem[];
    float* e2s = (float*)(smem + E2S_OFF);
    const uint32_t sb = smem_u32(smem);
    const int tid  = threadIdx.x;
    const int mb   = blockIdx.x;
    const int wid  = tid >> 5;
    const int lane = tid & 31;
    const int wm   = wid & 3;        // m strip (16 rows)
    const int wn   = wid >> 2;       // n strip (128 cols)
    const int g    = lane >> 2;      // group id 0..7
    const int cc   = lane & 3;       // thread in group

    // ---- B staging (chunk = 16 k-columns) ----
    auto stageB = [&](int c, int buf) {
        const int k0 = c * 16;
#pragma unroll
        for (int i = 0; i < 4; i++) {
            int e = tid + i * 512;
            int lim = e >> 10;
            int r = e & 1023;
            int n = r >> 1, q = r & 1;
            const __half* src = (lim ? g_B1 : g_B0) +
                                (size_t)n * 128 + k0 + q * 8;
            cpa16(sb + BS_OFF + buf * BBUF_STR + lim * BLO_OFF +
                      (uint32_t)(n * 48 + q * 16), src);
        }
        cpa_commit();
    };

    // ---- group 0: A fp32 tile (32KB, contiguous rows) ----
    {
        const float* Abase = A + (size_t)mb * 64 * 128;
#pragma unroll
        for (int i = 0; i < 4; i++) {
            int e = tid + i * 512;      // 16B piece index, 0..2047
            cpa16(sb + AF32_OFF + (uint32_t)e * 16, Abase + e * 4);
        }
        cpa_commit();
    }
    // ---- group 1: B chunk 0 ----
    stageB(0, 0);

    for (int i = tid; i < NCODE; i += 512) e2s[i] = g_e2[i];

    // ---- wait for A (B0 may still be in flight), convert to limbs ----
    cpa_wait1();
    __syncthreads();
    {
        const float2* Af = (const float2*)(smem + AF32_OFF);
#pragma unroll
        for (int it = 0; it < 8; it++) {
            int e = tid + it * 512;     // half2-pair index, 0..4095
            int m = e >> 6, j = e & 63; // row, k-pair (k = 2j)
            float2 v = Af[m * 64 + j];
            __half hx = __float2half_rn(v.x), hy = __float2half_rn(v.y);
            __half lx = __float2half_rn(v.x - __half2float(hx));
            __half ly = __float2half_rn(v.y - __half2float(hy));
            uint32_t off = (uint32_t)(AL_OFF + (j >> 3) * ACH_STR +
                                      m * 48 + (j & 7) * 4);
            *(__half2*)(smem + off)           = __halves2half2(hx, hy);
            *(__half2*)(smem + off + ALO_OFF) = __halves2half2(lx, ly);
        }
    }

    float acc[16][4];
#pragma unroll
    for (int i = 0; i < 16; i++)
#pragma unroll
        for (int j = 0; j < 4; j++) acc[i][j] = 0.0f;

    for (int c = 0; c < 8; c++) {
        cpa_wait0();
        __syncthreads();
        if (c < 7) stageB(c + 1, (c + 1) & 1);

        const __half* A0 = (const __half*)(smem + AL_OFF + c * ACH_STR);
        const __half* A1 = A0 + 1536;   // ALO_OFF bytes
        const __half* B0 = (const __half*)(smem + BS_OFF + (c & 1) * BBUF_STR);
        const __half* B1 = B0 + 12288;  // BLO_OFF bytes

        unsigned ah[4], al[4];
        {
            const int r0 = (wm * 16 + g) * 24;
            const int r8 = (wm * 16 + g + 8) * 24;
            ah[0] = *(const unsigned*)(A0 + r0 + 2 * cc);
            ah[1] = *(const unsigned*)(A0 + r8 + 2 * cc);
            ah[2] = *(const unsigned*)(A0 + r0 + 2 * cc + 8);
            ah[3] = *(const unsigned*)(A0 + r8 + 2 * cc + 8);
            al[0] = *(const unsigned*)(A1 + r0 + 2 * cc);
            al[1] = *(const unsigned*)(A1 + r8 + 2 * cc);
            al[2] = *(const unsigned*)(A1 + r0 + 2 * cc + 8);
            al[3] = *(const unsigned*)(A1 + r8 + 2 * cc + 8);
        }
#pragma unroll
        for (int nb = 0; nb < 16; nb++) {
            const int nrow = (wn * 128 + nb * 8 + g) * 24;
            unsigned bh0 = *(const unsigned*)(B0 + nrow + 2 * cc);
            unsigned bh1 = *(const unsigned*)(B0 + nrow + 2 * cc + 8);
            unsigned bl0 = *(const unsigned*)(B1 + nrow + 2 * cc);
            unsigned bl1 = *(const unsigned*)(B1 + nrow + 2 * cc + 8);
            mma16(acc[nb], ah, bh0, bh1);   // A_hi * B_hi
            mma16(acc[nb], ah, bl0, bl1);   // A_hi * B_lo
            mma16(acc[nb], al, bh0, bh1);   // A_lo * B_hi
        }
    }
    __syncthreads();   // all warps done reading tiles before sd overlays them

    // ---- dump raw dot' to sd (scalar 4B stores; odd stride) ----
    // ---- + padded e2 copy into dead AF32 region (bit-identical values) ----
    float* sd  = (float*)(smem + SD_OFF);
    float* e2p = (float*)(smem + AF32_OFF);
    e2p[tid + ((tid >> 6) << 2)] = e2s[tid];     // tid 0..511 covers codes 0..511
    {
        const int row0 = wm * 16 + g;
#pragma unroll
        for (int nb = 0; nb < 16; nb++) {
            const int col  = wn * 128 + nb * 8 + 2 * cc;
            const int colp = col + ((col >> 6) << 2);   // +4 pad per 64 cols
            float* p0 = &sd[(size_t)row0 * SD_STRIDE + colp];
            float* p1 = &sd[(size_t)(row0 + 8) * SD_STRIDE + colp];
            p0[0] = acc[nb][0];
            p0[1] = acc[nb][1];
            p1[0] = acc[nb][2];
            p1[1] = acc[nb][3];
        }
    }
    __syncthreads();

    // ---- row scan: 8 threads/row, 64 CONSECUTIVE cols per thread ----
    const int t   = tid & 7;
    const int rid = tid >> 3;
    const int row_g = mb * 64 + rid;

    // ks2 + dot with code 512 (fp32 from original inputs)
    float ks2 = 0.0f, dt = 0.0f;
    {
        const float4* kr = (const float4*)A + (size_t)row_g * 32;
        const float4* er = (const float4*)E + (size_t)512 * 32;
#pragma unroll
        for (int j = 0; j < 4; j++) {
            float4 a = kr[t * 4 + j];
            float4 e = __ldg(&er[t * 4 + j]);
            ks2 = fmaf(a.x, a.x, ks2); ks2 = fmaf(a.y, a.y, ks2);
            ks2 = fmaf(a.z, a.z, ks2); ks2 = fmaf(a.w, a.w, ks2);
            dt  = fmaf(a.x, e.x, dt);  dt  = fmaf(a.y, e.y, dt);
            dt  = fmaf(a.z, e.z, dt);  dt  = fmaf(a.w, e.w, dt);
        }
#pragma unroll
        for (int o = 1; o < 8; o <<= 1) {
            ks2 += __shfl_xor_sync(0xffffffffu, ks2, o);
            dt  += __shfl_xor_sync(0xffffffffu, dt, o);
        }
    }
    float d512 = (ks2 + e2s[512]) - 2.0f * dt;

    // dot' = 512*dot  =>  2*dot = dot'/256, exact power-of-2 rescale
    const float RS = 1.0f / 256.0f;
    const float* sdr = sd + (size_t)rid * SD_STRIDE + t * 68;
    const float* e2r = e2p + t * 68;
    const int jbase = t * 64;
    float best = 3.4e38f;
    int   bi = 0;
    float dprev = 0.0f, dfirst = 0.0f;
    unsigned w0 = 0, w1 = 0;
#pragma unroll
    for (int i = 0; i < 64; i++) {
        float d = (ks2 + e2r[i]) - RS * sdr[i];   // identical shape to R10-13
        if (i == 0) {
            dfirst = d;
        } else {
            unsigned bit = (dprev > d) ? 1u : 0u;
            const int p = i - 1;
            if (p < 32) w0 |= bit << p;
            else        w1 |= bit << (p - 32);
        }
        if (d < best) { best = d; bi = jbase + i; }
        dprev = d;
    }
    {
        float nf = __shfl_down_sync(0xffffffffu, dfirst, 1, 8);
        unsigned bitb = ((t < 7) && (dprev > nf)) ? 1u : 0u;
        w1 |= bitb << 31;
    }
    *(ull*)&g_move[(size_t)row_g * 16 + 2 * t] = (ull)w0 | ((ull)w1 << 32);

#pragma unroll
    for (int o = 1; o < 8; o <<= 1) {
        float ov = __shfl_xor_sync(0xffffffffu, best, o);
        int   oi = __shfl_xor_sync(0xffffffffu, bi, o);
        if (ov < best || (ov == best && oi < bi)) { best = ov; bi = oi; }
    }
    if (d512 < best) bi = 512;
    if (t == 0) g_minidx[row_g] = bi;
}

// ============================================================
// K3a: chunk transition tables (fully unrolled dependent chain)
// ============================================================
__global__ __launch_bounds__(512) void k_scantbl(void) {
    const int c   = blockIdx.x;     // 0..14
    const int b   = blockIdx.y;
    const int tid = threadIdx.x;
    __shared__ unsigned mw[64][16];
    const int t0 = c * 64 + 1;
#pragma unroll
    for (int r = 0; r < 2; r++) {
        int i = tid + r * 512;
        mw[i >> 4][i & 15] =
            g_move[(size_t)(b * 1024 + t0 + (i >> 4)) * 16 + (i & 15)];
    }
    __syncthreads();
    int ind = tid;
#pragma unroll
    for (int s = 0; s < 64; s++) ind += (mw[s][ind >> 5] >> (ind & 31)) & 1;
    g_tbl[((size_t)b * 15 + c) * 512 + tid] = (unsigned short)ind;
}

// ============================================================
// K3b: entry states. One block per batch; all 15 tables staged
// into smem (coalesced), then thread 0's 15-hop walk is LDS
// (~30cyc/hop) instead of L2 (~600cyc/hop).
// ============================================================
__global__ __launch_bounds__(512) void k_entries(const unsigned char* __restrict__ mask) {
    __shared__ unsigned short tb[15 * 512];
    const int b   = blockIdx.x;
    const int tid = threadIdx.x;
    // coalesced stage: 15*512 u16 = 7680 u16 = 1920 uint4 loads
    const uint4* src = (const uint4*)(g_tbl + (size_t)b * 15 * 512);
    uint4* dst = (uint4*)tb;
    for (int i = tid; i < 15 * 512 / 8; i += 512) dst[i] = src[i];
    __syncthreads();
    if (tid == 0) {
        int ind = g_minidx[b * 1024];
        if (ind > 511) ind = 511;
        if (mask[b]) ind = 0;
        g_ent[b * 16] = ind;
#pragma unroll
        for (int c = 0; c < 15; c++) {
            ind = tb[c * 512 + ind];
            g_ent[b * 16 + c + 1] = ind;
        }
    }
}

// ============================================================
// K3c: emit enc. grid (16, 64) x 64 threads, 4KB smem/block,
// entry state precomputed -> no table walk on the critical path.
// ============================================================
__global__ __launch_bounds__(64) void k_emit_enc(void) {
    const int c   = blockIdx.x;     // 0..15
    const int b   = blockIdx.y;
    const int tid = threadIdx.x;
    __shared__ unsigned mw[63][16];
    const int t0 = c * 64 + 1;
    for (int i = tid; i < 63 * 16; i += 64)
        mw[i >> 4][i & 15] =
            g_move[(size_t)(b * 1024 + t0 + (i >> 4)) * 16 + (i & 15)];
    __syncthreads();
    int ind = g_ent[b * 16 + c];
    for (int s = 0; s < tid; s++) ind += (mw[s][ind >> 5] >> (ind & 31)) & 1;
    g_enc[b * 1024 + c * 64 + tid] = ind;
}

// ============================================================
// K4: fused gathers + losses + key_hard + energy. Warp per (b,t).
// ============================================================
__global__ __launch_bounds__(256) void k_final(const float* __restrict__ ks,
                                               const float* __restrict__ emb,
                                               float* __restrict__ out) {
    const int row  = blockIdx.x * 8 + (threadIdx.x >> 5);
    const int lane = threadIdx.x & 31;
    const float4* k4 = (const float4*)ks + (size_t)row * 32;
    const float4* e4 = (const float4*)emb;

    int here = g_enc[row];
    int nxt  = here + 1; if (nxt > 511) nxt = 511;
    int mi   = g_minidx[row];

    float4 a  = k4[lane];
    float4 eh = e4[(size_t)here * 32 + lane];
    float4 en = e4[(size_t)nxt * 32 + lane];
    float4 em = e4[(size_t)mi * 32 + lane];

    float sh, sn, sm;
    {
        float d0 = a.x - eh.x, d1 = a.y - eh.y, d2 = a.z - eh.z, d3 = a.w - eh.w;
        sh = d0 * d0; sh = fmaf(d1, d1, sh); sh = fmaf(d2, d2, sh); sh = fmaf(d3, d3, sh);
    }
    {
        float d0 = a.x - en.x, d1 = a.y - en.y, d2 = a.z - en.z, d3 = a.w - en.w;
        sn = d0 * d0; sn = fmaf(d1, d1, sn); sn = fmaf(d2, d2, sn); sn = fmaf(d3, d3, sn);
    }
    {
        float d0 = a.x - em.x, d1 = a.y - em.y, d2 = a.z - em.z, d3 = a.w - em.w;
        sm = d0 * d0; sm = fmaf(d1, d1, sm); sm = fmaf(d2, d2, sm); sm = fmaf(d3, d3, sm);
    }
#pragma unroll
    for (int off = 16; off; off >>= 1) {
        sh += __shfl_xor_sync(0xffffffffu, sh, off);
        sn += __shfl_xor_sync(0xffffffffu, sn, off);
        sm += __shfl_xor_sync(0xffffffffu, sm, off);
    }

    float4 o;
    o.x = a.x + (eh.x - a.x);
    o.y = a.y + (eh.y - a.y);
    o.z = a.z + (eh.z - a.z);
    o.w = a.w + (eh.w - a.w);
    ((float4*)(out + OFF_KH))[(size_t)row * 32 + lane] = o;

    if (lane == 0) {
        float Lh = sh + sh * 0.2f;
        float Ln = sn + sn * 0.2f;
        float Lm = sm + sm * 0.2f;
        float dif = sn - sh;
        float energy = dif + dif * 0.2f;
        float lmh = (Lm < Lh) ? Lm : 0.0f;
        float lmn = (Lm < Ln) ? Lm : 0.0f;
        out[OFF_LH  + row] = (Lh - Ln) - lmh;
        out[OFF_LNX + row] = (Ln - Lh) - lmn;
        out[OFF_ENC + row] = (float)here;
        g_energy[row] = energy;
    }
}

// ============================================================
// K5: per-batch reductions
// ============================================================
__global__ __launch_bounds__(256) void k_reduce_b(void) {
    const int b   = blockIdx.x;
    const int tid = threadIdx.x;
    __shared__ float sE[256], sL[256];
    __shared__ int   sMn[256], sMx[256];
    const float* eb = g_energy + b * 1024;
    const int*   cb = g_enc + b * 1024;

    float aE = 0.0f, aL = 0.0f;
    int mn = 1 << 30, mx = -1;
    for (int t = tid; t < 1024; t += 256) {
        aE += eb[t];
        int cv = cb[t];
        mn = min(mn, cv);
        mx = max(mx, cv);
    }
    const float EPS = (float)(1e-6 / 512.0);
    for (int t = tid + 1; t < 1024; t += 256) {
        float ch = (cb[t] != cb[t - 1]) ? 0.0f : (eb[t] - eb[t - 1]);
        aL += fmaxf(ch + EPS, 0.0f);
    }
    sE[tid] = aE; sL[tid] = aL; sMn[tid] = mn; sMx[tid] = mx;
    __syncthreads();
    for (int s = 128; s; s >>= 1) {
        if (tid < s) {
            sE[tid] += sE[tid + s];
            sL[tid] += sL[tid + s];
            sMn[tid] = min(sMn[tid], sMn[tid + s]);
            sMx[tid] = max(sMx[tid], sMx[tid + s]);
        }
        __syncthreads();
    }
    if (tid == 0) {
        g_pE[b]  = sE[0];
        g_pL[b]  = sL[0];
        g_rng[b] = sMx[0] - sMn[0];
    }
}

// ============================================================
// K6: final scalars
// ============================================================
__global__ void k_scalars(float* __restrict__ out) {
    int tid = threadIdx.x;  // 64
    __shared__ float sE[64], sL[64];
    __shared__ int   sR[64];
    sE[tid] = g_pE[tid]; sL[tid] = g_pL[tid]; sR[tid] = g_rng[tid];
    __syncthreads();
    for (int s = 32; s; s >>= 1) {
        if (tid < s) {
            sE[tid] += sE[tid + s];
            sL[tid] += sL[tid + s];
            sR[tid] = max(sR[tid], sR[tid + s]);
        }
        __syncthreads();
    }
    if (tid == 0) {
        out[OFF_EM]  = sE[0] / 65536.0f;
        out[OFF_LED] = sL[0] / 65472.0f;
        out[OFF_V]   = (float)sR[0];
    }
}

// ============================================================
extern "C" void kernel_launch(void* const* d_in, const int* in_sizes, int n_in,
                              void* d_out, int out_size) {
    const float* ks = nullptr;
    const float* emb = nullptr;
    const unsigned char* mask = nullptr;
    for (int i = 0; i < n_in; i++) {
        if (in_sizes[i] == ROWS * D_)        ks   = (const float*)d_in[i];
        else if (in_sizes[i] == NCODE * D_)  emb  = (const float*)d_in[i];
        else if (in_sizes[i] == B_)          mask = (const unsigned char*)d_in[i];
    }
    float* out = (float*)d_out;

    cudaFuncSetAttribute(k_gemm_fused,
                         cudaFuncAttributeMaxDynamicSharedMemorySize, SMEM_BYTES);

    k_split_b<<<(NCODE * 32 + 255) / 256, 256>>>(emb);
    k_gemm_fused<<<ROWS / 64, 512, SMEM_BYTES>>>(ks, emb);
    k_scantbl<<<dim3(15, B_), 512>>>();
    k_entries<<<B_, 512>>>(mask);
    k_emit_enc<<<dim3(16, B_), 64>>>();
    k_final<<<ROWS / 8, 256>>>(ks, emb, out);
    k_reduce_b<<<B_, 256>>>();
    k_scalars<<<1, 64>>>(out);
}